// round 2
// baseline (speedup 1.0000x reference)
#include <cuda_runtime.h>
#include <cuda_bf16.h>
#include <math.h>

// ---------------------------------------------------------------------------
// Problem constants
// ---------------------------------------------------------------------------
#define L1   10752
#define NF   21
#define L2   769
#define IMG  257
#define LTXT 512          // L2 - IMG
#define Hd   1536
#define NH   12
#define Dh   128
#define L3   32
#define CAd  768
#define EPSV 1e-6f

// ---------------------------------------------------------------------------
// Scratch (static __device__ globals — allocation-free per harness rules)
// ---------------------------------------------------------------------------
__device__ float g_Q   [(size_t)L1 * Hd];
__device__ float g_K   [(size_t)LTXT * Hd];
__device__ float g_V   [(size_t)LTXT * Hd];
__device__ float g_Kimg[(size_t)IMG * Hd];
__device__ float g_Vimg[(size_t)IMG * Hd];
__device__ float g_IPK [(size_t)NF * L3 * Hd];
__device__ float g_IPV [(size_t)NF * L3 * Hd];
__device__ float g_C   [(size_t)L1 * Hd];

// ---------------------------------------------------------------------------
// SGEMM: C[m,n] = bias[n] + sum_k A[m,k] * W[n,k]   (both K-contiguous, "NT")
// BM=BN=128, BK=16, 256 threads, 8x8 per-thread microtile.
// N and K are always multiples of 128/16 here; only M needs guarding.
// ---------------------------------------------------------------------------
#define BM 128
#define BN 128
#define BK 16

__global__ __launch_bounds__(256) void sgemm_nt_bias(
    const float* __restrict__ A, const float* __restrict__ W,
    const float* __restrict__ bias, float* __restrict__ C,
    int M, int Nn, int K)
{
    __shared__ float As[BK][BM];
    __shared__ float Bs[BK][BN];

    const int tid = threadIdx.x;
    const int bm = blockIdx.y * BM;
    const int bn = blockIdx.x * BN;
    const int tx = tid & 15;
    const int ty = tid >> 4;

    float acc[8][8];
#pragma unroll
    for (int i = 0; i < 8; i++)
#pragma unroll
        for (int j = 0; j < 8; j++) acc[i][j] = 0.f;

    const int lrow = tid >> 2;          // 0..63
    const int lcol = (tid & 3) * 4;     // 0,4,8,12

    for (int k0 = 0; k0 < K; k0 += BK) {
        // load A tile (guard M)
#pragma unroll
        for (int p = 0; p < 2; p++) {
            int row = p * 64 + lrow;
            int gr  = bm + row;
            float4 a4 = make_float4(0.f, 0.f, 0.f, 0.f);
            if (gr < M) a4 = *(const float4*)(A + (size_t)gr * K + k0 + lcol);
            As[lcol + 0][row] = a4.x;
            As[lcol + 1][row] = a4.y;
            As[lcol + 2][row] = a4.z;
            As[lcol + 3][row] = a4.w;
        }
        // load W tile (N always full)
#pragma unroll
        for (int p = 0; p < 2; p++) {
            int row = p * 64 + lrow;
            int gr  = bn + row;
            float4 b4 = *(const float4*)(W + (size_t)gr * K + k0 + lcol);
            Bs[lcol + 0][row] = b4.x;
            Bs[lcol + 1][row] = b4.y;
            Bs[lcol + 2][row] = b4.z;
            Bs[lcol + 3][row] = b4.w;
        }
        __syncthreads();

#pragma unroll
        for (int k = 0; k < BK; k++) {
            float af[8], bf[8];
            float4 a0 = *(const float4*)&As[k][ty * 8];
            float4 a1 = *(const float4*)&As[k][ty * 8 + 4];
            float4 b0 = *(const float4*)&Bs[k][tx * 8];
            float4 b1 = *(const float4*)&Bs[k][tx * 8 + 4];
            af[0]=a0.x; af[1]=a0.y; af[2]=a0.z; af[3]=a0.w;
            af[4]=a1.x; af[5]=a1.y; af[6]=a1.z; af[7]=a1.w;
            bf[0]=b0.x; bf[1]=b0.y; bf[2]=b0.z; bf[3]=b0.w;
            bf[4]=b1.x; bf[5]=b1.y; bf[6]=b1.z; bf[7]=b1.w;
#pragma unroll
            for (int i = 0; i < 8; i++)
#pragma unroll
                for (int j = 0; j < 8; j++)
                    acc[i][j] = fmaf(af[i], bf[j], acc[i][j]);
        }
        __syncthreads();
    }

#pragma unroll
    for (int i = 0; i < 8; i++) {
        int gr = bm + ty * 8 + i;
        if (gr < M) {
#pragma unroll
            for (int j = 0; j < 8; j += 4) {
                int gc = bn + tx * 8 + j;
                float4 o;
                float b0 = bias ? bias[gc + 0] : 0.f;
                float b1 = bias ? bias[gc + 1] : 0.f;
                float b2 = bias ? bias[gc + 2] : 0.f;
                float b3 = bias ? bias[gc + 3] : 0.f;
                o.x = acc[i][j + 0] + b0;
                o.y = acc[i][j + 1] + b1;
                o.z = acc[i][j + 2] + b2;
                o.w = acc[i][j + 3] + b3;
                *(float4*)(C + (size_t)gr * Nn + gc) = o;
            }
        }
    }
}

// ---------------------------------------------------------------------------
// RMSNorm over rows of length 1536, in place:  x = x * rsqrt(mean(x^2)+eps) * w
// one block (256 threads) per row
// ---------------------------------------------------------------------------
__global__ __launch_bounds__(256) void rmsnorm_kernel(
    float* __restrict__ X, const float* __restrict__ w)
{
    const int row = blockIdx.x;
    float* x = X + (size_t)row * Hd;
    const int tid = threadIdx.x;

    float v[6];
    float ss = 0.f;
#pragma unroll
    for (int i = 0; i < 6; i++) {
        v[i] = x[tid + i * 256];
        ss = fmaf(v[i], v[i], ss);
    }
#pragma unroll
    for (int o = 16; o > 0; o >>= 1) ss += __shfl_xor_sync(0xffffffffu, ss, o);

    __shared__ float warp_s[8];
    __shared__ float s_scale;
    if ((tid & 31) == 0) warp_s[tid >> 5] = ss;
    __syncthreads();
    if (tid < 8) {
        float t = warp_s[tid];
#pragma unroll
        for (int o = 4; o > 0; o >>= 1) t += __shfl_xor_sync(0xffu, t, o);
        if (tid == 0) s_scale = rsqrtf(t * (1.f / (float)Hd) + EPSV);
    }
    __syncthreads();
    float sc = s_scale;
#pragma unroll
    for (int i = 0; i < 6; i++)
        x[tid + i * 256] = v[i] * sc * w[tid + i * 256];
}

// ---------------------------------------------------------------------------
// Fused 3-phase attention.
// grid = (L1/32, NH), block = 128 threads.
// Each 4-lane group owns one query row; each lane owns 32 of the 128 d-values.
// Phases: 0 = img (257 keys, no mask), 1 = txt (masked by context_lens[0]),
//         2 = audio (per-frame 32 keys, masked by audio_context_lens[f]).
// Each phase runs its own online softmax; normalized results are summed.
// ---------------------------------------------------------------------------
#define TQ 32
#define CHK 32

__global__ __launch_bounds__(128) void attn_kernel(
    const float* __restrict__ Q,
    const float* __restrict__ Ktxt, const float* __restrict__ Vtxt,
    const float* __restrict__ Kimg, const float* __restrict__ Vimg,
    const float* __restrict__ IPK,  const float* __restrict__ IPV,
    const int* __restrict__ ctx_lens, const int* __restrict__ audio_lens,
    float* __restrict__ Out)
{
    __shared__ float sK[CHK][Dh];
    __shared__ float sV[CHK][Dh];

    const int head  = blockIdx.y;
    const int qbase = blockIdx.x * TQ;
    const int tid   = threadIdx.x;
    const int qi    = tid >> 2;   // 0..31 query within tile
    const int dg    = tid & 3;    // 0..3  d-group (32 floats each)
    const int q     = qbase + qi;

    // preload my query slice (32 floats) into registers
    float4 qreg[8];
    const float* qptr = Q + (size_t)q * Hd + head * Dh + dg * 32;
#pragma unroll
    for (int i = 0; i < 8; i++) qreg[i] = *(const float4*)(qptr + i * 4);

    const float scale = 0.08838834764831845f;   // 1/sqrt(128)

    float out[32];
#pragma unroll
    for (int i = 0; i < 32; i++) out[i] = 0.f;

    const int frame = qbase / 512;

    for (int phase = 0; phase < 3; phase++) {
        const float *Kp, *Vp;
        int klen;
        if (phase == 0)      { Kp = Kimg; Vp = Vimg; klen = IMG; }
        else if (phase == 1) { Kp = Ktxt; Vp = Vtxt; klen = ctx_lens[0]; }
        else {
            Kp = IPK + (size_t)frame * L3 * Hd;
            Vp = IPV + (size_t)frame * L3 * Hd;
            klen = audio_lens[frame];
        }

        float m = -1e30f, l = 0.f;
        float acc[32];
#pragma unroll
        for (int i = 0; i < 32; i++) acc[i] = 0.f;

        for (int kb = 0; kb < klen; kb += CHK) {
            const int cl = min(CHK, klen - kb);

            __syncthreads();   // protect previous sK/sV consumers
            // cooperative load of K/V chunk: 1024 float4 over 128 threads
#pragma unroll
            for (int p = 0; p < 8; p++) {
                int idx = tid + p * 128;
                int r = idx >> 5;            // key row (32 float4 per row)
                int c = (idx & 31) * 4;
                if (r < cl) {
                    *(float4*)&sK[r][c] = *(const float4*)(Kp + (size_t)(kb + r) * Hd + head * Dh + c);
                    *(float4*)&sV[r][c] = *(const float4*)(Vp + (size_t)(kb + r) * Hd + head * Dh + c);
                }
            }
            __syncthreads();

            // scores for this chunk
            float s[CHK];
#pragma unroll
            for (int j = 0; j < CHK; j++) s[j] = -1e30f;
#pragma unroll
            for (int j = 0; j < CHK; j++) {
                if (j < cl) {  // cl is block-uniform: no divergence
                    const float4* k4 = (const float4*)&sK[j][dg * 32];
                    float p = 0.f;
#pragma unroll
                    for (int i = 0; i < 8; i++) {
                        float4 kk = k4[i];
                        p = fmaf(qreg[i].x, kk.x, p);
                        p = fmaf(qreg[i].y, kk.y, p);
                        p = fmaf(qreg[i].z, kk.z, p);
                        p = fmaf(qreg[i].w, kk.w, p);
                    }
                    p += __shfl_xor_sync(0xffffffffu, p, 1);
                    p += __shfl_xor_sync(0xffffffffu, p, 2);
                    s[j] = p * scale;
                }
            }

            float cmax = -1e30f;
#pragma unroll
            for (int j = 0; j < CHK; j++) cmax = fmaxf(cmax, s[j]);

            float mnew = fmaxf(m, cmax);
            float corr = __expf(m - mnew);
            l *= corr;
#pragma unroll
            for (int i = 0; i < 32; i++) acc[i] *= corr;

#pragma unroll
            for (int j = 0; j < CHK; j++) {
                if (j < cl) {
                    float p = __expf(s[j] - mnew);
                    l += p;
                    const float4* v4 = (const float4*)&sV[j][dg * 32];
#pragma unroll
                    for (int i = 0; i < 8; i++) {
                        float4 vv = v4[i];
                        acc[4*i+0] = fmaf(p, vv.x, acc[4*i+0]);
                        acc[4*i+1] = fmaf(p, vv.y, acc[4*i+1]);
                        acc[4*i+2] = fmaf(p, vv.z, acc[4*i+2]);
                        acc[4*i+3] = fmaf(p, vv.w, acc[4*i+3]);
                    }
                }
            }
            m = mnew;
        }

        float rl = 1.f / l;
#pragma unroll
        for (int i = 0; i < 32; i++) out[i] = fmaf(acc[i], rl, out[i]);
    }

    float* optr = Out + (size_t)q * Hd + head * Dh + dg * 32;
#pragma unroll
    for (int i = 0; i < 8; i++)
        *(float4*)(optr + i * 4) =
            make_float4(out[4*i], out[4*i+1], out[4*i+2], out[4*i+3]);
}

// ---------------------------------------------------------------------------
// Launch
// ---------------------------------------------------------------------------
extern "C" void kernel_launch(void* const* d_in, const int* in_sizes, int n_in,
                              void* d_out, int out_size)
{
    const float* x          = (const float*)d_in[0];
    const float* context    = (const float*)d_in[1];
    const float* audio_proj = (const float*)d_in[2];
    const float* Wq  = (const float*)d_in[3];
    const float* bq  = (const float*)d_in[4];
    const float* Wk  = (const float*)d_in[5];
    const float* bk  = (const float*)d_in[6];
    const float* Wv  = (const float*)d_in[7];
    const float* bv  = (const float*)d_in[8];
    const float* Wki = (const float*)d_in[9];
    const float* bki = (const float*)d_in[10];
    const float* Wvi = (const float*)d_in[11];
    const float* bvi = (const float*)d_in[12];
    const float* Wo  = (const float*)d_in[13];
    const float* bo  = (const float*)d_in[14];
    const float* nq  = (const float*)d_in[15];
    const float* nk  = (const float*)d_in[16];
    const float* nki = (const float*)d_in[17];
    const float* Wkp = (const float*)d_in[18];
    const float* Wvp = (const float*)d_in[19];
    const int* ctx_lens   = (const int*)d_in[20];
    const int* audio_lens = (const int*)d_in[21];
    float* out = (float*)d_out;

    float *gQ, *gK, *gV, *gKi, *gVi, *gIPK, *gIPV, *gC;
    cudaGetSymbolAddress((void**)&gQ,   g_Q);
    cudaGetSymbolAddress((void**)&gK,   g_K);
    cudaGetSymbolAddress((void**)&gV,   g_V);
    cudaGetSymbolAddress((void**)&gKi,  g_Kimg);
    cudaGetSymbolAddress((void**)&gVi,  g_Vimg);
    cudaGetSymbolAddress((void**)&gIPK, g_IPK);
    cudaGetSymbolAddress((void**)&gIPV, g_IPV);
    cudaGetSymbolAddress((void**)&gC,   g_C);

    const float* ctx_txt = context + (size_t)IMG * Hd;

    // Projections
    sgemm_nt_bias<<<dim3(Hd / BN, L1 / BM), 256>>>(x, Wq, bq, gQ, L1, Hd, Hd);
    rmsnorm_kernel<<<L1, 256>>>(gQ, nq);

    sgemm_nt_bias<<<dim3(Hd / BN, LTXT / BM), 256>>>(ctx_txt, Wk, bk, gK, LTXT, Hd, Hd);
    rmsnorm_kernel<<<LTXT, 256>>>(gK, nk);
    sgemm_nt_bias<<<dim3(Hd / BN, LTXT / BM), 256>>>(ctx_txt, Wv, bv, gV, LTXT, Hd, Hd);

    sgemm_nt_bias<<<dim3(Hd / BN, (IMG + BM - 1) / BM), 256>>>(context, Wki, bki, gKi, IMG, Hd, Hd);
    rmsnorm_kernel<<<IMG, 256>>>(gKi, nki);
    sgemm_nt_bias<<<dim3(Hd / BN, (IMG + BM - 1) / BM), 256>>>(context, Wvi, bvi, gVi, IMG, Hd, Hd);

    const int AM = NF * L3;   // 672 audio rows
    sgemm_nt_bias<<<dim3(Hd / BN, (AM + BM - 1) / BM), 256>>>(audio_proj, Wkp, nullptr, gIPK, AM, Hd, CAd);
    sgemm_nt_bias<<<dim3(Hd / BN, (AM + BM - 1) / BM), 256>>>(audio_proj, Wvp, nullptr, gIPV, AM, Hd, CAd);

    // Fused three-way attention -> combined
    attn_kernel<<<dim3(L1 / TQ, NH), 128>>>(gQ, gK, gV, gKi, gVi, gIPK, gIPV,
                                            ctx_lens, audio_lens, gC);

    // Output projection
    sgemm_nt_bias<<<dim3(Hd / BN, L1 / BM), 256>>>(gC, Wo, bo, out, L1, Hd, Hd);
}

// round 3
// speedup vs baseline: 1.2189x; 1.2189x over previous
#include <cuda_runtime.h>
#include <cuda_bf16.h>
#include <math.h>

// ---------------------------------------------------------------------------
// Problem constants
// ---------------------------------------------------------------------------
#define L1   10752
#define NF   21
#define L2   769
#define IMG  257
#define LTXT 512          // L2 - IMG
#define Hd   1536
#define NH   12
#define Dh   128
#define L3   32
#define CAd  768
#define EPSV 1e-6f

// ---------------------------------------------------------------------------
// Scratch (static __device__ globals — allocation-free per harness rules)
// ---------------------------------------------------------------------------
__device__ float g_Q   [(size_t)L1 * Hd];
__device__ float g_K   [(size_t)LTXT * Hd];
__device__ float g_V   [(size_t)LTXT * Hd];
__device__ float g_Kimg[(size_t)IMG * Hd];
__device__ float g_Vimg[(size_t)IMG * Hd];
__device__ float g_IPK [(size_t)NF * L3 * Hd];
__device__ float g_IPV [(size_t)NF * L3 * Hd];
__device__ float g_C   [(size_t)L1 * Hd];

// ---------------------------------------------------------------------------
// Tensor-core GEMM (bf16x3 split precision):
//   C[m,n] = bias[n] + sum_k A[m,k] * W[n,k]     (both K-contiguous, "NT")
// Each fp32 value a is split a = hi + lo (both bf16); product approximated by
// hi*hi + hi*lo + lo*hi  (error ~1e-5 relative). fp32 accumulate in MMA.
// BM=BN=128, BK=32, 256 threads = 8 warps (4m x 2n), warp tile 32x64.
// mma.sync.aligned.m16n8k16.row.col.f32.bf16.bf16.f32
// ---------------------------------------------------------------------------
#define GBM 128
#define GBN 128
#define GBK 32

__device__ __forceinline__ void mma_bf16(float* d, const unsigned* a, const unsigned* b)
{
    asm volatile(
        "mma.sync.aligned.m16n8k16.row.col.f32.bf16.bf16.f32 "
        "{%0,%1,%2,%3}, {%4,%5,%6,%7}, {%8,%9}, {%0,%1,%2,%3};\n"
        : "+f"(d[0]), "+f"(d[1]), "+f"(d[2]), "+f"(d[3])
        : "r"(a[0]), "r"(a[1]), "r"(a[2]), "r"(a[3]), "r"(b[0]), "r"(b[1]));
}

__device__ __forceinline__ void ldsm_x4(unsigned* r, const void* p)
{
    unsigned addr = (unsigned)__cvta_generic_to_shared(p);
    asm volatile(
        "ldmatrix.sync.aligned.m8n8.x4.shared.b16 {%0,%1,%2,%3}, [%4];\n"
        : "=r"(r[0]), "=r"(r[1]), "=r"(r[2]), "=r"(r[3]) : "r"(addr));
}

// swizzled smem offset (bf16 elements) for a [128][32] bf16 tile.
// 16B chunk index (k>>3) is XORed with (row>>1)&3 -> conflict-free ldmatrix.
__device__ __forceinline__ int swz_off(int r, int k)
{
    return r * GBK + ((((k >> 3) ^ (r >> 1)) & 3) << 3) + (k & 7);
}

__device__ __forceinline__ unsigned pack_bf16(__nv_bfloat16 lo, __nv_bfloat16 hi)
{
    return ((unsigned)__bfloat16_as_ushort(hi) << 16) | (unsigned)__bfloat16_as_ushort(lo);
}

__global__ __launch_bounds__(256) void gemm_bf16x3(
    const float* __restrict__ A, const float* __restrict__ W,
    const float* __restrict__ bias, float* __restrict__ C,
    int M, int Nn, int K)
{
    __shared__ __nv_bfloat16 sAh[GBM * GBK];
    __shared__ __nv_bfloat16 sAl[GBM * GBK];
    __shared__ __nv_bfloat16 sBh[GBN * GBK];
    __shared__ __nv_bfloat16 sBl[GBN * GBK];

    const int tid  = threadIdx.x;
    const int warp = tid >> 5;
    const int lane = tid & 31;
    const int wm   = warp >> 1;          // 0..3
    const int wn   = warp & 1;           // 0..1
    const int bm   = blockIdx.y * GBM;
    const int bn   = blockIdx.x * GBN;

    float acc[2][8][4];
#pragma unroll
    for (int i = 0; i < 2; i++)
#pragma unroll
        for (int j = 0; j < 8; j++)
#pragma unroll
            for (int t = 0; t < 4; t++) acc[i][j][t] = 0.f;

    for (int k0 = 0; k0 < K; k0 += GBK) {
        // ---- load fp32 tiles, split to hi/lo bf16, store swizzled ----
#pragma unroll
        for (int p = 0; p < 4; p++) {
            int idx = tid + p * 256;         // 0..1023 (float4 index)
            int r   = idx >> 3;              // 0..127
            int c4  = (idx & 7) << 2;        // k: 0,4,...,28

            // A tile (guard M)
            float4 a = make_float4(0.f, 0.f, 0.f, 0.f);
            if (bm + r < M) a = *(const float4*)(A + (size_t)(bm + r) * K + k0 + c4);
            __nv_bfloat16 h0 = __float2bfloat16_rn(a.x);
            __nv_bfloat16 h1 = __float2bfloat16_rn(a.y);
            __nv_bfloat16 h2 = __float2bfloat16_rn(a.z);
            __nv_bfloat16 h3 = __float2bfloat16_rn(a.w);
            __nv_bfloat16 l0 = __float2bfloat16_rn(a.x - __bfloat162float(h0));
            __nv_bfloat16 l1 = __float2bfloat16_rn(a.y - __bfloat162float(h1));
            __nv_bfloat16 l2 = __float2bfloat16_rn(a.z - __bfloat162float(h2));
            __nv_bfloat16 l3 = __float2bfloat16_rn(a.w - __bfloat162float(h3));
            int off = swz_off(r, c4);
            *(uint2*)&sAh[off] = make_uint2(pack_bf16(h0, h1), pack_bf16(h2, h3));
            *(uint2*)&sAl[off] = make_uint2(pack_bf16(l0, l1), pack_bf16(l2, l3));

            // B tile (Nn always multiple of 128 -> no guard)
            float4 b = *(const float4*)(W + (size_t)(bn + r) * K + k0 + c4);
            __nv_bfloat16 g0 = __float2bfloat16_rn(b.x);
            __nv_bfloat16 g1 = __float2bfloat16_rn(b.y);
            __nv_bfloat16 g2 = __float2bfloat16_rn(b.z);
            __nv_bfloat16 g3 = __float2bfloat16_rn(b.w);
            __nv_bfloat16 m0 = __float2bfloat16_rn(b.x - __bfloat162float(g0));
            __nv_bfloat16 m1 = __float2bfloat16_rn(b.y - __bfloat162float(g1));
            __nv_bfloat16 m2 = __float2bfloat16_rn(b.z - __bfloat162float(g2));
            __nv_bfloat16 m3 = __float2bfloat16_rn(b.w - __bfloat162float(g3));
            *(uint2*)&sBh[off] = make_uint2(pack_bf16(g0, g1), pack_bf16(g2, g3));
            *(uint2*)&sBl[off] = make_uint2(pack_bf16(m0, m1), pack_bf16(m2, m3));
        }
        __syncthreads();

        // ---- two k16 steps of MMA ----
#pragma unroll
        for (int ks = 0; ks < 2; ks++) {
            const int kk   = ks * 16;
            const int kfrg = kk + ((lane >> 4) << 3);     // k for ldmatrix addr
            const int rfrg = lane & 15;

            unsigned ah[2][4], al[2][4];
#pragma unroll
            for (int i = 0; i < 2; i++) {
                int r = wm * 32 + i * 16 + rfrg;
                ldsm_x4(ah[i], &sAh[swz_off(r, kfrg)]);
                ldsm_x4(al[i], &sAl[swz_off(r, kfrg)]);
            }

            unsigned bh[8][2], bl[8][2];
#pragma unroll
            for (int p = 0; p < 4; p++) {
                int n = wn * 64 + p * 16 + rfrg;
                unsigned t[4];
                ldsm_x4(t, &sBh[swz_off(n, kfrg)]);
                bh[p*2][0] = t[0]; bh[p*2+1][0] = t[1];
                bh[p*2][1] = t[2]; bh[p*2+1][1] = t[3];
                ldsm_x4(t, &sBl[swz_off(n, kfrg)]);
                bl[p*2][0] = t[0]; bl[p*2+1][0] = t[1];
                bl[p*2][1] = t[2]; bl[p*2+1][1] = t[3];
            }

#pragma unroll
            for (int i = 0; i < 2; i++)
#pragma unroll
                for (int j = 0; j < 8; j++) {
                    mma_bf16(acc[i][j], ah[i], bh[j]);   // hi*hi
                    mma_bf16(acc[i][j], ah[i], bl[j]);   // hi*lo
                    mma_bf16(acc[i][j], al[i], bh[j]);   // lo*hi
                }
        }
        __syncthreads();
    }

    // ---- epilogue ----
#pragma unroll
    for (int i = 0; i < 2; i++) {
        int r0 = bm + wm * 32 + i * 16 + (lane >> 2);
        int r1 = r0 + 8;
#pragma unroll
        for (int j = 0; j < 8; j++) {
            int c  = bn + wn * 64 + j * 8 + (lane & 3) * 2;
            float b0 = bias ? bias[c]     : 0.f;
            float b1 = bias ? bias[c + 1] : 0.f;
            if (r0 < M) {
                C[(size_t)r0 * Nn + c]     = acc[i][j][0] + b0;
                C[(size_t)r0 * Nn + c + 1] = acc[i][j][1] + b1;
            }
            if (r1 < M) {
                C[(size_t)r1 * Nn + c]     = acc[i][j][2] + b0;
                C[(size_t)r1 * Nn + c + 1] = acc[i][j][3] + b1;
            }
        }
    }
}

// ---------------------------------------------------------------------------
// RMSNorm over rows of length 1536, in place:  x = x * rsqrt(mean(x^2)+eps) * w
// one block (256 threads) per row
// ---------------------------------------------------------------------------
__global__ __launch_bounds__(256) void rmsnorm_kernel(
    float* __restrict__ X, const float* __restrict__ w)
{
    const int row = blockIdx.x;
    float* x = X + (size_t)row * Hd;
    const int tid = threadIdx.x;

    float v[6];
    float ss = 0.f;
#pragma unroll
    for (int i = 0; i < 6; i++) {
        v[i] = x[tid + i * 256];
        ss = fmaf(v[i], v[i], ss);
    }
#pragma unroll
    for (int o = 16; o > 0; o >>= 1) ss += __shfl_xor_sync(0xffffffffu, ss, o);

    __shared__ float warp_s[8];
    __shared__ float s_scale;
    if ((tid & 31) == 0) warp_s[tid >> 5] = ss;
    __syncthreads();
    if (tid < 8) {
        float t = warp_s[tid];
#pragma unroll
        for (int o = 4; o > 0; o >>= 1) t += __shfl_xor_sync(0xffu, t, o);
        if (tid == 0) s_scale = rsqrtf(t * (1.f / (float)Hd) + EPSV);
    }
    __syncthreads();
    float sc = s_scale;
#pragma unroll
    for (int i = 0; i < 6; i++)
        x[tid + i * 256] = v[i] * sc * w[tid + i * 256];
}

// ---------------------------------------------------------------------------
// Fused 3-phase attention (unchanged from R2).
// grid = (L1/32, NH), block = 128 threads.
// ---------------------------------------------------------------------------
#define TQ 32
#define CHK 32

__global__ __launch_bounds__(128) void attn_kernel(
    const float* __restrict__ Q,
    const float* __restrict__ Ktxt, const float* __restrict__ Vtxt,
    const float* __restrict__ Kimg, const float* __restrict__ Vimg,
    const float* __restrict__ IPK,  const float* __restrict__ IPV,
    const int* __restrict__ ctx_lens, const int* __restrict__ audio_lens,
    float* __restrict__ Out)
{
    __shared__ float sK[CHK][Dh];
    __shared__ float sV[CHK][Dh];

    const int head  = blockIdx.y;
    const int qbase = blockIdx.x * TQ;
    const int tid   = threadIdx.x;
    const int qi    = tid >> 2;   // 0..31 query within tile
    const int dg    = tid & 3;    // 0..3  d-group (32 floats each)
    const int q     = qbase + qi;

    float4 qreg[8];
    const float* qptr = Q + (size_t)q * Hd + head * Dh + dg * 32;
#pragma unroll
    for (int i = 0; i < 8; i++) qreg[i] = *(const float4*)(qptr + i * 4);

    const float scale = 0.08838834764831845f;   // 1/sqrt(128)

    float out[32];
#pragma unroll
    for (int i = 0; i < 32; i++) out[i] = 0.f;

    const int frame = qbase / 512;

    for (int phase = 0; phase < 3; phase++) {
        const float *Kp, *Vp;
        int klen;
        if (phase == 0)      { Kp = Kimg; Vp = Vimg; klen = IMG; }
        else if (phase == 1) { Kp = Ktxt; Vp = Vtxt; klen = ctx_lens[0]; }
        else {
            Kp = IPK + (size_t)frame * L3 * Hd;
            Vp = IPV + (size_t)frame * L3 * Hd;
            klen = audio_lens[frame];
        }

        float m = -1e30f, l = 0.f;
        float acc[32];
#pragma unroll
        for (int i = 0; i < 32; i++) acc[i] = 0.f;

        for (int kb = 0; kb < klen; kb += CHK) {
            const int cl = min(CHK, klen - kb);

            __syncthreads();
#pragma unroll
            for (int p = 0; p < 8; p++) {
                int idx = tid + p * 128;
                int r = idx >> 5;
                int c = (idx & 31) * 4;
                if (r < cl) {
                    *(float4*)&sK[r][c] = *(const float4*)(Kp + (size_t)(kb + r) * Hd + head * Dh + c);
                    *(float4*)&sV[r][c] = *(const float4*)(Vp + (size_t)(kb + r) * Hd + head * Dh + c);
                }
            }
            __syncthreads();

            float s[CHK];
#pragma unroll
            for (int j = 0; j < CHK; j++) s[j] = -1e30f;
#pragma unroll
            for (int j = 0; j < CHK; j++) {
                if (j < cl) {
                    const float4* k4 = (const float4*)&sK[j][dg * 32];
                    float p = 0.f;
#pragma unroll
                    for (int i = 0; i < 8; i++) {
                        float4 kk = k4[i];
                        p = fmaf(qreg[i].x, kk.x, p);
                        p = fmaf(qreg[i].y, kk.y, p);
                        p = fmaf(qreg[i].z, kk.z, p);
                        p = fmaf(qreg[i].w, kk.w, p);
                    }
                    p += __shfl_xor_sync(0xffffffffu, p, 1);
                    p += __shfl_xor_sync(0xffffffffu, p, 2);
                    s[j] = p * scale;
                }
            }

            float cmax = -1e30f;
#pragma unroll
            for (int j = 0; j < CHK; j++) cmax = fmaxf(cmax, s[j]);

            float mnew = fmaxf(m, cmax);
            float corr = __expf(m - mnew);
            l *= corr;
#pragma unroll
            for (int i = 0; i < 32; i++) acc[i] *= corr;

#pragma unroll
            for (int j = 0; j < CHK; j++) {
                if (j < cl) {
                    float p = __expf(s[j] - mnew);
                    l += p;
                    const float4* v4 = (const float4*)&sV[j][dg * 32];
#pragma unroll
                    for (int i = 0; i < 8; i++) {
                        float4 vv = v4[i];
                        acc[4*i+0] = fmaf(p, vv.x, acc[4*i+0]);
                        acc[4*i+1] = fmaf(p, vv.y, acc[4*i+1]);
                        acc[4*i+2] = fmaf(p, vv.z, acc[4*i+2]);
                        acc[4*i+3] = fmaf(p, vv.w, acc[4*i+3]);
                    }
                }
            }
            m = mnew;
        }

        float rl = 1.f / l;
#pragma unroll
        for (int i = 0; i < 32; i++) out[i] = fmaf(acc[i], rl, out[i]);
    }

    float* optr = Out + (size_t)q * Hd + head * Dh + dg * 32;
#pragma unroll
    for (int i = 0; i < 8; i++)
        *(float4*)(optr + i * 4) =
            make_float4(out[4*i], out[4*i+1], out[4*i+2], out[4*i+3]);
}

// ---------------------------------------------------------------------------
// Launch
// ---------------------------------------------------------------------------
extern "C" void kernel_launch(void* const* d_in, const int* in_sizes, int n_in,
                              void* d_out, int out_size)
{
    const float* x          = (const float*)d_in[0];
    const float* context    = (const float*)d_in[1];
    const float* audio_proj = (const float*)d_in[2];
    const float* Wq  = (const float*)d_in[3];
    const float* bq  = (const float*)d_in[4];
    const float* Wk  = (const float*)d_in[5];
    const float* bk  = (const float*)d_in[6];
    const float* Wv  = (const float*)d_in[7];
    const float* bv  = (const float*)d_in[8];
    const float* Wki = (const float*)d_in[9];
    const float* bki = (const float*)d_in[10];
    const float* Wvi = (const float*)d_in[11];
    const float* bvi = (const float*)d_in[12];
    const float* Wo  = (const float*)d_in[13];
    const float* bo  = (const float*)d_in[14];
    const float* nq  = (const float*)d_in[15];
    const float* nk  = (const float*)d_in[16];
    const float* nki = (const float*)d_in[17];
    const float* Wkp = (const float*)d_in[18];
    const float* Wvp = (const float*)d_in[19];
    const int* ctx_lens   = (const int*)d_in[20];
    const int* audio_lens = (const int*)d_in[21];
    float* out = (float*)d_out;

    float *gQ, *gK, *gV, *gKi, *gVi, *gIPK, *gIPV, *gC;
    cudaGetSymbolAddress((void**)&gQ,   g_Q);
    cudaGetSymbolAddress((void**)&gK,   g_K);
    cudaGetSymbolAddress((void**)&gV,   g_V);
    cudaGetSymbolAddress((void**)&gKi,  g_Kimg);
    cudaGetSymbolAddress((void**)&gVi,  g_Vimg);
    cudaGetSymbolAddress((void**)&gIPK, g_IPK);
    cudaGetSymbolAddress((void**)&gIPV, g_IPV);
    cudaGetSymbolAddress((void**)&gC,   g_C);

    const float* ctx_txt = context + (size_t)IMG * Hd;

    // Projections (tensor-core bf16x3)
    gemm_bf16x3<<<dim3(Hd / GBN, L1 / GBM), 256>>>(x, Wq, bq, gQ, L1, Hd, Hd);
    rmsnorm_kernel<<<L1, 256>>>(gQ, nq);

    gemm_bf16x3<<<dim3(Hd / GBN, LTXT / GBM), 256>>>(ctx_txt, Wk, bk, gK, LTXT, Hd, Hd);
    rmsnorm_kernel<<<LTXT, 256>>>(gK, nk);
    gemm_bf16x3<<<dim3(Hd / GBN, LTXT / GBM), 256>>>(ctx_txt, Wv, bv, gV, LTXT, Hd, Hd);

    gemm_bf16x3<<<dim3(Hd / GBN, (IMG + GBM - 1) / GBM), 256>>>(context, Wki, bki, gKi, IMG, Hd, Hd);
    rmsnorm_kernel<<<IMG, 256>>>(gKi, nki);
    gemm_bf16x3<<<dim3(Hd / GBN, (IMG + GBM - 1) / GBM), 256>>>(context, Wvi, bvi, gVi, IMG, Hd, Hd);

    const int AM = NF * L3;   // 672 audio rows
    gemm_bf16x3<<<dim3(Hd / GBN, (AM + GBM - 1) / GBM), 256>>>(audio_proj, Wkp, nullptr, gIPK, AM, Hd, CAd);
    gemm_bf16x3<<<dim3(Hd / GBN, (AM + GBM - 1) / GBM), 256>>>(audio_proj, Wvp, nullptr, gIPV, AM, Hd, CAd);

    // Fused three-way attention -> combined
    attn_kernel<<<dim3(L1 / TQ, NH), 128>>>(gQ, gK, gV, gKi, gVi, gIPK, gIPV,
                                            ctx_lens, audio_lens, gC);

    // Output projection
    gemm_bf16x3<<<dim3(Hd / GBN, L1 / GBM), 256>>>(gC, Wo, bo, out, L1, Hd, Hd);
}

// round 4
// speedup vs baseline: 1.2361x; 1.0141x over previous
#include <cuda_runtime.h>
#include <cuda_bf16.h>
#include <math.h>

// ---------------------------------------------------------------------------
// Problem constants
// ---------------------------------------------------------------------------
#define L1   10752
#define NF   21
#define L2   769
#define IMG  257
#define LTXT 512          // L2 - IMG
#define Hd   1536
#define NH   12
#define Dh   128
#define L3   32
#define CAd  768
#define EPSV 1e-6f

// ---------------------------------------------------------------------------
// Scratch (static __device__ globals — allocation-free per harness rules)
// ---------------------------------------------------------------------------
__device__ float g_Q   [(size_t)L1 * Hd];
__device__ float g_K   [(size_t)LTXT * Hd];
__device__ float g_V   [(size_t)LTXT * Hd];
__device__ float g_Kimg[(size_t)IMG * Hd];
__device__ float g_Vimg[(size_t)IMG * Hd];
__device__ float g_IPK [(size_t)NF * L3 * Hd];
__device__ float g_IPV [(size_t)NF * L3 * Hd];

// bf16 hi/lo split operands
__device__ __nv_bfloat16 g_xh [(size_t)L1 * Hd];
__device__ __nv_bfloat16 g_xl [(size_t)L1 * Hd];
__device__ __nv_bfloat16 g_cth[(size_t)L2 * Hd];
__device__ __nv_bfloat16 g_ctl[(size_t)L2 * Hd];
__device__ __nv_bfloat16 g_aph[(size_t)NF * L3 * CAd];
__device__ __nv_bfloat16 g_apl[(size_t)NF * L3 * CAd];
__device__ __nv_bfloat16 g_Wh [6][(size_t)Hd * Hd];   // q,k,v,ki,vi,o
__device__ __nv_bfloat16 g_Wl [6][(size_t)Hd * Hd];
__device__ __nv_bfloat16 g_Wph[2][(size_t)Hd * CAd];  // kp,vp
__device__ __nv_bfloat16 g_Wpl[2][(size_t)Hd * CAd];
__device__ __nv_bfloat16 g_Ch [(size_t)L1 * Hd];
__device__ __nv_bfloat16 g_Cl [(size_t)L1 * Hd];

// ---------------------------------------------------------------------------
// Helpers
// ---------------------------------------------------------------------------
__device__ __forceinline__ unsigned pack_bf16(__nv_bfloat16 lo, __nv_bfloat16 hi)
{
    return ((unsigned)__bfloat16_as_ushort(hi) << 16) | (unsigned)__bfloat16_as_ushort(lo);
}

__device__ __forceinline__ void mma_bf16(float* d, const unsigned* a, const unsigned* b)
{
    asm volatile(
        "mma.sync.aligned.m16n8k16.row.col.f32.bf16.bf16.f32 "
        "{%0,%1,%2,%3}, {%4,%5,%6,%7}, {%8,%9}, {%0,%1,%2,%3};\n"
        : "+f"(d[0]), "+f"(d[1]), "+f"(d[2]), "+f"(d[3])
        : "r"(a[0]), "r"(a[1]), "r"(a[2]), "r"(a[3]), "r"(b[0]), "r"(b[1]));
}

__device__ __forceinline__ void ldsm_x4(unsigned* r, const void* p)
{
    unsigned addr = (unsigned)__cvta_generic_to_shared(p);
    asm volatile(
        "ldmatrix.sync.aligned.m8n8.x4.shared.b16 {%0,%1,%2,%3}, [%4];\n"
        : "=r"(r[0]), "=r"(r[1]), "=r"(r[2]), "=r"(r[3]) : "r"(addr));
}

__device__ __forceinline__ void cp_async16(void* dst, const void* src, int szbytes)
{
    unsigned d = (unsigned)__cvta_generic_to_shared(dst);
    asm volatile("cp.async.cg.shared.global [%0], [%1], 16, %2;\n"
                 :: "r"(d), "l"(src), "r"(szbytes));
}

// ---------------------------------------------------------------------------
// Elementwise fp32 -> (hi, lo) bf16 split
// ---------------------------------------------------------------------------
__global__ __launch_bounds__(256) void split_kernel(
    const float4* __restrict__ src, uint2* __restrict__ hi,
    uint2* __restrict__ lo, int n4)
{
    int i = blockIdx.x * 256 + threadIdx.x;
    if (i >= n4) return;
    float4 a = src[i];
    __nv_bfloat16 h0 = __float2bfloat16_rn(a.x);
    __nv_bfloat16 h1 = __float2bfloat16_rn(a.y);
    __nv_bfloat16 h2 = __float2bfloat16_rn(a.z);
    __nv_bfloat16 h3 = __float2bfloat16_rn(a.w);
    __nv_bfloat16 l0 = __float2bfloat16_rn(a.x - __bfloat162float(h0));
    __nv_bfloat16 l1 = __float2bfloat16_rn(a.y - __bfloat162float(h1));
    __nv_bfloat16 l2 = __float2bfloat16_rn(a.z - __bfloat162float(h2));
    __nv_bfloat16 l3 = __float2bfloat16_rn(a.w - __bfloat162float(h3));
    hi[i] = make_uint2(pack_bf16(h0, h1), pack_bf16(h2, h3));
    lo[i] = make_uint2(pack_bf16(l0, l1), pack_bf16(l2, l3));
}

// ---------------------------------------------------------------------------
// Pipelined tensor-core GEMM (bf16x3 split precision, pre-split operands):
//   C[m,n] = bias[n] + sum_k A[m,k] * W[n,k]     (both K-contiguous, "NT")
// BM=BN=128, BK=16, 256 threads = 8 warps (4m x 2n), warp tile 32x64.
// cp.async double-buffered (2 stages, 32KB static smem).
// ---------------------------------------------------------------------------
#define GBM 128
#define GBN 128
#define GBK 16
#define TILE_E (GBM * GBK)

// swizzled element offset into a [128][16] bf16 tile (16B-chunk XOR)
__device__ __forceinline__ int swz16(int r, int k)
{
    int chunk = (k >> 3) ^ ((r >> 2) & 1);
    return r * GBK + (chunk << 3) + (k & 7);
}

__global__ __launch_bounds__(256) void gemm_pipe(
    const __nv_bfloat16* __restrict__ Ah, const __nv_bfloat16* __restrict__ Al,
    const __nv_bfloat16* __restrict__ Bh, const __nv_bfloat16* __restrict__ Bl,
    const float* __restrict__ bias, float* __restrict__ C,
    int M, int Nn, int K)
{
    __shared__ __nv_bfloat16 s[2][4][TILE_E];   // stage x {Ah,Al,Bh,Bl}

    const int tid  = threadIdx.x;
    const int warp = tid >> 5;
    const int lane = tid & 31;
    const int wm   = warp >> 1;          // 0..3
    const int wn   = warp & 1;           // 0..1
    const int bm   = blockIdx.y * GBM;
    const int bn   = blockIdx.x * GBN;

    // per-thread load slot: row 0..127, k-chunk 0/8
    const int lr   = tid >> 1;
    const int lc   = (tid & 1) << 3;
    const int loff = swz16(lr, lc);
    const bool va  = (bm + lr) < M;
    const int  ra  = va ? (bm + lr) : 0;
    const int  rb  = bn + lr;
    const int  sza = va ? 16 : 0;

    float acc[2][8][4];
#pragma unroll
    for (int i = 0; i < 2; i++)
#pragma unroll
        for (int j = 0; j < 8; j++)
#pragma unroll
            for (int t = 0; t < 4; t++) acc[i][j][t] = 0.f;

    const int nt = K / GBK;

    // preload stage 0
    {
        cp_async16(&s[0][0][loff], Ah + (size_t)ra * K + lc, sza);
        cp_async16(&s[0][1][loff], Al + (size_t)ra * K + lc, sza);
        cp_async16(&s[0][2][loff], Bh + (size_t)rb * K + lc, 16);
        cp_async16(&s[0][3][loff], Bl + (size_t)rb * K + lc, 16);
        asm volatile("cp.async.commit_group;\n" ::: "memory");
    }

    const int rfrg = lane & 15;
    const int kf   = (lane >> 4) << 3;

    for (int t = 0; t < nt; t++) {
        if (t + 1 < nt) {
            const int st = (t + 1) & 1;
            const int k0 = (t + 1) * GBK;
            cp_async16(&s[st][0][loff], Ah + (size_t)ra * K + k0 + lc, sza);
            cp_async16(&s[st][1][loff], Al + (size_t)ra * K + k0 + lc, sza);
            cp_async16(&s[st][2][loff], Bh + (size_t)rb * K + k0 + lc, 16);
            cp_async16(&s[st][3][loff], Bl + (size_t)rb * K + k0 + lc, 16);
            asm volatile("cp.async.commit_group;\n" ::: "memory");
            asm volatile("cp.async.wait_group 1;\n" ::: "memory");
        } else {
            asm volatile("cp.async.wait_group 0;\n" ::: "memory");
        }
        __syncthreads();

        const __nv_bfloat16* pAh = s[t & 1][0];
        const __nv_bfloat16* pAl = s[t & 1][1];
        const __nv_bfloat16* pBh = s[t & 1][2];
        const __nv_bfloat16* pBl = s[t & 1][3];

        unsigned ah[2][4], al[2][4];
#pragma unroll
        for (int i = 0; i < 2; i++) {
            int r = wm * 32 + i * 16 + rfrg;
            ldsm_x4(ah[i], pAh + swz16(r, kf));
            ldsm_x4(al[i], pAl + swz16(r, kf));
        }

        unsigned bh[8][2], bl[8][2];
#pragma unroll
        for (int p = 0; p < 4; p++) {
            int n = wn * 64 + p * 16 + rfrg;
            unsigned tt[4];
            ldsm_x4(tt, pBh + swz16(n, kf));
            bh[p*2][0] = tt[0]; bh[p*2+1][0] = tt[1];
            bh[p*2][1] = tt[2]; bh[p*2+1][1] = tt[3];
            ldsm_x4(tt, pBl + swz16(n, kf));
            bl[p*2][0] = tt[0]; bl[p*2+1][0] = tt[1];
            bl[p*2][1] = tt[2]; bl[p*2+1][1] = tt[3];
        }

#pragma unroll
        for (int i = 0; i < 2; i++)
#pragma unroll
            for (int j = 0; j < 8; j++) {
                mma_bf16(acc[i][j], ah[i], bh[j]);   // hi*hi
                mma_bf16(acc[i][j], ah[i], bl[j]);   // hi*lo
                mma_bf16(acc[i][j], al[i], bh[j]);   // lo*hi
            }
        __syncthreads();
    }

    // ---- epilogue ----
#pragma unroll
    for (int i = 0; i < 2; i++) {
        int r0 = bm + wm * 32 + i * 16 + (lane >> 2);
        int r1 = r0 + 8;
#pragma unroll
        for (int j = 0; j < 8; j++) {
            int c  = bn + wn * 64 + j * 8 + (lane & 3) * 2;
            float b0 = bias ? bias[c]     : 0.f;
            float b1 = bias ? bias[c + 1] : 0.f;
            if (r0 < M) {
                C[(size_t)r0 * Nn + c]     = acc[i][j][0] + b0;
                C[(size_t)r0 * Nn + c + 1] = acc[i][j][1] + b1;
            }
            if (r1 < M) {
                C[(size_t)r1 * Nn + c]     = acc[i][j][2] + b0;
                C[(size_t)r1 * Nn + c + 1] = acc[i][j][3] + b1;
            }
        }
    }
}

// ---------------------------------------------------------------------------
// RMSNorm over rows of length 1536, in place
// ---------------------------------------------------------------------------
__global__ __launch_bounds__(256) void rmsnorm_kernel(
    float* __restrict__ X, const float* __restrict__ w)
{
    const int row = blockIdx.x;
    float* x = X + (size_t)row * Hd;
    const int tid = threadIdx.x;

    float v[6];
    float ss = 0.f;
#pragma unroll
    for (int i = 0; i < 6; i++) {
        v[i] = x[tid + i * 256];
        ss = fmaf(v[i], v[i], ss);
    }
#pragma unroll
    for (int o = 16; o > 0; o >>= 1) ss += __shfl_xor_sync(0xffffffffu, ss, o);

    __shared__ float warp_s[8];
    __shared__ float s_scale;
    if ((tid & 31) == 0) warp_s[tid >> 5] = ss;
    __syncthreads();
    if (tid < 8) {
        float t = warp_s[tid];
#pragma unroll
        for (int o = 4; o > 0; o >>= 1) t += __shfl_xor_sync(0xffu, t, o);
        if (tid == 0) s_scale = rsqrtf(t * (1.f / (float)Hd) + EPSV);
    }
    __syncthreads();
    float sc = s_scale;
#pragma unroll
    for (int i = 0; i < 6; i++)
        x[tid + i * 256] = v[i] * sc * w[tid + i * 256];
}

// ---------------------------------------------------------------------------
// Fused 3-phase attention. Output written directly as hi/lo bf16 split
// (consumed by the O-projection GEMM).
// grid = (L1/32, NH), block = 128 threads.
// ---------------------------------------------------------------------------
#define TQ 32
#define CHK 32

__global__ __launch_bounds__(128) void attn_kernel(
    const float* __restrict__ Q,
    const float* __restrict__ Ktxt, const float* __restrict__ Vtxt,
    const float* __restrict__ Kimg, const float* __restrict__ Vimg,
    const float* __restrict__ IPK,  const float* __restrict__ IPV,
    const int* __restrict__ ctx_lens, const int* __restrict__ audio_lens,
    __nv_bfloat16* __restrict__ Ch, __nv_bfloat16* __restrict__ Cl)
{
    __shared__ float sK[CHK][Dh];
    __shared__ float sV[CHK][Dh];

    const int head  = blockIdx.y;
    const int qbase = blockIdx.x * TQ;
    const int tid   = threadIdx.x;
    const int qi    = tid >> 2;   // 0..31 query within tile
    const int dg    = tid & 3;    // 0..3  d-group (32 floats each)
    const int q     = qbase + qi;

    float4 qreg[8];
    const float* qptr = Q + (size_t)q * Hd + head * Dh + dg * 32;
#pragma unroll
    for (int i = 0; i < 8; i++) qreg[i] = *(const float4*)(qptr + i * 4);

    const float scale = 0.08838834764831845f;   // 1/sqrt(128)

    float out[32];
#pragma unroll
    for (int i = 0; i < 32; i++) out[i] = 0.f;

    const int frame = qbase / 512;

    for (int phase = 0; phase < 3; phase++) {
        const float *Kp, *Vp;
        int klen;
        if (phase == 0)      { Kp = Kimg; Vp = Vimg; klen = IMG; }
        else if (phase == 1) { Kp = Ktxt; Vp = Vtxt; klen = ctx_lens[0]; }
        else {
            Kp = IPK + (size_t)frame * L3 * Hd;
            Vp = IPV + (size_t)frame * L3 * Hd;
            klen = audio_lens[frame];
        }

        float m = -1e30f, l = 0.f;
        float acc[32];
#pragma unroll
        for (int i = 0; i < 32; i++) acc[i] = 0.f;

        for (int kb = 0; kb < klen; kb += CHK) {
            const int cl = min(CHK, klen - kb);

            __syncthreads();
#pragma unroll
            for (int p = 0; p < 8; p++) {
                int idx = tid + p * 128;
                int r = idx >> 5;
                int c = (idx & 31) * 4;
                if (r < cl) {
                    *(float4*)&sK[r][c] = *(const float4*)(Kp + (size_t)(kb + r) * Hd + head * Dh + c);
                    *(float4*)&sV[r][c] = *(const float4*)(Vp + (size_t)(kb + r) * Hd + head * Dh + c);
                }
            }
            __syncthreads();

            float s[CHK];
#pragma unroll
            for (int j = 0; j < CHK; j++) s[j] = -1e30f;
#pragma unroll
            for (int j = 0; j < CHK; j++) {
                if (j < cl) {
                    const float4* k4 = (const float4*)&sK[j][dg * 32];
                    float p = 0.f;
#pragma unroll
                    for (int i = 0; i < 8; i++) {
                        float4 kk = k4[i];
                        p = fmaf(qreg[i].x, kk.x, p);
                        p = fmaf(qreg[i].y, kk.y, p);
                        p = fmaf(qreg[i].z, kk.z, p);
                        p = fmaf(qreg[i].w, kk.w, p);
                    }
                    p += __shfl_xor_sync(0xffffffffu, p, 1);
                    p += __shfl_xor_sync(0xffffffffu, p, 2);
                    s[j] = p * scale;
                }
            }

            float cmax = -1e30f;
#pragma unroll
            for (int j = 0; j < CHK; j++) cmax = fmaxf(cmax, s[j]);

            float mnew = fmaxf(m, cmax);
            float corr = __expf(m - mnew);
            l *= corr;
#pragma unroll
            for (int i = 0; i < 32; i++) acc[i] *= corr;

#pragma unroll
            for (int j = 0; j < CHK; j++) {
                if (j < cl) {
                    float p = __expf(s[j] - mnew);
                    l += p;
                    const float4* v4 = (const float4*)&sV[j][dg * 32];
#pragma unroll
                    for (int i = 0; i < 8; i++) {
                        float4 vv = v4[i];
                        acc[4*i+0] = fmaf(p, vv.x, acc[4*i+0]);
                        acc[4*i+1] = fmaf(p, vv.y, acc[4*i+1]);
                        acc[4*i+2] = fmaf(p, vv.z, acc[4*i+2]);
                        acc[4*i+3] = fmaf(p, vv.w, acc[4*i+3]);
                    }
                }
            }
            m = mnew;
        }

        float rl = 1.f / l;
#pragma unroll
        for (int i = 0; i < 32; i++) out[i] = fmaf(acc[i], rl, out[i]);
    }

    const size_t off = (size_t)q * Hd + head * Dh + dg * 32;
#pragma unroll
    for (int i = 0; i < 8; i++) {
        float x0 = out[4*i], x1 = out[4*i+1], x2 = out[4*i+2], x3 = out[4*i+3];
        __nv_bfloat16 h0 = __float2bfloat16_rn(x0);
        __nv_bfloat16 h1 = __float2bfloat16_rn(x1);
        __nv_bfloat16 h2 = __float2bfloat16_rn(x2);
        __nv_bfloat16 h3 = __float2bfloat16_rn(x3);
        __nv_bfloat16 l0 = __float2bfloat16_rn(x0 - __bfloat162float(h0));
        __nv_bfloat16 l1 = __float2bfloat16_rn(x1 - __bfloat162float(h1));
        __nv_bfloat16 l2 = __float2bfloat16_rn(x2 - __bfloat162float(h2));
        __nv_bfloat16 l3 = __float2bfloat16_rn(x3 - __bfloat162float(h3));
        *(uint2*)&Ch[off + i * 4] = make_uint2(pack_bf16(h0, h1), pack_bf16(h2, h3));
        *(uint2*)&Cl[off + i * 4] = make_uint2(pack_bf16(l0, l1), pack_bf16(l2, l3));
    }
}

// ---------------------------------------------------------------------------
// Launch
// ---------------------------------------------------------------------------
static void run_split(const float* src, __nv_bfloat16* hi, __nv_bfloat16* lo, size_t n)
{
    int n4 = (int)(n / 4);
    split_kernel<<<(n4 + 255) / 256, 256>>>(
        (const float4*)src, (uint2*)hi, (uint2*)lo, n4);
}

extern "C" void kernel_launch(void* const* d_in, const int* in_sizes, int n_in,
                              void* d_out, int out_size)
{
    const float* x          = (const float*)d_in[0];
    const float* context    = (const float*)d_in[1];
    const float* audio_proj = (const float*)d_in[2];
    const float* Wq  = (const float*)d_in[3];
    const float* bq  = (const float*)d_in[4];
    const float* Wk  = (const float*)d_in[5];
    const float* bk  = (const float*)d_in[6];
    const float* Wv  = (const float*)d_in[7];
    const float* bv  = (const float*)d_in[8];
    const float* Wki = (const float*)d_in[9];
    const float* bki = (const float*)d_in[10];
    const float* Wvi = (const float*)d_in[11];
    const float* bvi = (const float*)d_in[12];
    const float* Wo  = (const float*)d_in[13];
    const float* bo  = (const float*)d_in[14];
    const float* nq  = (const float*)d_in[15];
    const float* nk  = (const float*)d_in[16];
    const float* nki = (const float*)d_in[17];
    const float* Wkp = (const float*)d_in[18];
    const float* Wvp = (const float*)d_in[19];
    const int* ctx_lens   = (const int*)d_in[20];
    const int* audio_lens = (const int*)d_in[21];
    float* out = (float*)d_out;

    float *gQ, *gK, *gV, *gKi, *gVi, *gIPK, *gIPV;
    cudaGetSymbolAddress((void**)&gQ,   g_Q);
    cudaGetSymbolAddress((void**)&gK,   g_K);
    cudaGetSymbolAddress((void**)&gV,   g_V);
    cudaGetSymbolAddress((void**)&gKi,  g_Kimg);
    cudaGetSymbolAddress((void**)&gVi,  g_Vimg);
    cudaGetSymbolAddress((void**)&gIPK, g_IPK);
    cudaGetSymbolAddress((void**)&gIPV, g_IPV);

    __nv_bfloat16 *xh, *xl, *cth, *ctl, *aph, *apl, *Wh, *Wl, *Wph, *Wpl, *Chh, *Cll;
    cudaGetSymbolAddress((void**)&xh,  g_xh);
    cudaGetSymbolAddress((void**)&xl,  g_xl);
    cudaGetSymbolAddress((void**)&cth, g_cth);
    cudaGetSymbolAddress((void**)&ctl, g_ctl);
    cudaGetSymbolAddress((void**)&aph, g_aph);
    cudaGetSymbolAddress((void**)&apl, g_apl);
    cudaGetSymbolAddress((void**)&Wh,  g_Wh);
    cudaGetSymbolAddress((void**)&Wl,  g_Wl);
    cudaGetSymbolAddress((void**)&Wph, g_Wph);
    cudaGetSymbolAddress((void**)&Wpl, g_Wpl);
    cudaGetSymbolAddress((void**)&Chh, g_Ch);
    cudaGetSymbolAddress((void**)&Cll, g_Cl);

    const size_t WSZ  = (size_t)Hd * Hd;
    const size_t WPSZ = (size_t)Hd * CAd;

    // ---- split all GEMM operands to hi/lo bf16 ----
    run_split(x,          xh,            xl,            (size_t)L1 * Hd);
    run_split(context,    cth,           ctl,           (size_t)L2 * Hd);
    run_split(audio_proj, aph,           apl,           (size_t)NF * L3 * CAd);
    run_split(Wq,         Wh + 0 * WSZ,  Wl + 0 * WSZ,  WSZ);
    run_split(Wk,         Wh + 1 * WSZ,  Wl + 1 * WSZ,  WSZ);
    run_split(Wv,         Wh + 2 * WSZ,  Wl + 2 * WSZ,  WSZ);
    run_split(Wki,        Wh + 3 * WSZ,  Wl + 3 * WSZ,  WSZ);
    run_split(Wvi,        Wh + 4 * WSZ,  Wl + 4 * WSZ,  WSZ);
    run_split(Wo,         Wh + 5 * WSZ,  Wl + 5 * WSZ,  WSZ);
    run_split(Wkp,        Wph + 0 * WPSZ, Wpl + 0 * WPSZ, WPSZ);
    run_split(Wvp,        Wph + 1 * WPSZ, Wpl + 1 * WPSZ, WPSZ);

    const __nv_bfloat16* ctxth = cth + (size_t)IMG * Hd;
    const __nv_bfloat16* ctxtl = ctl + (size_t)IMG * Hd;

    // ---- projections ----
    gemm_pipe<<<dim3(Hd / GBN, L1 / GBM), 256>>>(
        xh, xl, Wh + 0 * WSZ, Wl + 0 * WSZ, bq, gQ, L1, Hd, Hd);
    rmsnorm_kernel<<<L1, 256>>>(gQ, nq);

    gemm_pipe<<<dim3(Hd / GBN, LTXT / GBM), 256>>>(
        ctxth, ctxtl, Wh + 1 * WSZ, Wl + 1 * WSZ, bk, gK, LTXT, Hd, Hd);
    rmsnorm_kernel<<<LTXT, 256>>>(gK, nk);
    gemm_pipe<<<dim3(Hd / GBN, LTXT / GBM), 256>>>(
        ctxth, ctxtl, Wh + 2 * WSZ, Wl + 2 * WSZ, bv, gV, LTXT, Hd, Hd);

    gemm_pipe<<<dim3(Hd / GBN, (IMG + GBM - 1) / GBM), 256>>>(
        cth, ctl, Wh + 3 * WSZ, Wl + 3 * WSZ, bki, gKi, IMG, Hd, Hd);
    rmsnorm_kernel<<<IMG, 256>>>(gKi, nki);
    gemm_pipe<<<dim3(Hd / GBN, (IMG + GBM - 1) / GBM), 256>>>(
        cth, ctl, Wh + 4 * WSZ, Wl + 4 * WSZ, bvi, gVi, IMG, Hd, Hd);

    const int AM = NF * L3;   // 672 audio rows
    gemm_pipe<<<dim3(Hd / GBN, (AM + GBM - 1) / GBM), 256>>>(
        aph, apl, Wph + 0 * WPSZ, Wpl + 0 * WPSZ, nullptr, gIPK, AM, Hd, CAd);
    gemm_pipe<<<dim3(Hd / GBN, (AM + GBM - 1) / GBM), 256>>>(
        aph, apl, Wph + 1 * WPSZ, Wpl + 1 * WPSZ, nullptr, gIPV, AM, Hd, CAd);

    // ---- fused three-way attention -> bf16 hi/lo combined ----
    attn_kernel<<<dim3(L1 / TQ, NH), 128>>>(gQ, gK, gV, gKi, gVi, gIPK, gIPV,
                                            ctx_lens, audio_lens, Chh, Cll);

    // ---- output projection ----
    gemm_pipe<<<dim3(Hd / GBN, L1 / GBM), 256>>>(
        Chh, Cll, Wh + 5 * WSZ, Wl + 5 * WSZ, bo, out, L1, Hd, Hd);
}

// round 7
// speedup vs baseline: 5.9719x; 4.8313x over previous
#include <cuda_runtime.h>
#include <cuda_bf16.h>
#include <math.h>

// ---------------------------------------------------------------------------
// Problem constants
// ---------------------------------------------------------------------------
#define L1   10752
#define NF   21
#define L2   769
#define IMG  257
#define LTXT 512          // L2 - IMG
#define Hd   1536
#define NH   12
#define Dh   128
#define L3   32
#define CAd  768
#define EPSV 1e-6f

// ---------------------------------------------------------------------------
// Scratch (static __device__ globals — allocation-free per harness rules)
// ---------------------------------------------------------------------------
__device__ float g_Q   [(size_t)L1 * Hd];
__device__ float g_K   [(size_t)LTXT * Hd];
__device__ float g_V   [(size_t)LTXT * Hd];
__device__ float g_Kimg[(size_t)IMG * Hd];
__device__ float g_Vimg[(size_t)IMG * Hd];
__device__ float g_IPK [(size_t)NF * L3 * Hd];
__device__ float g_IPV [(size_t)NF * L3 * Hd];

// bf16 hi/lo split operands for GEMMs
__device__ __nv_bfloat16 g_xh [(size_t)L1 * Hd];
__device__ __nv_bfloat16 g_xl [(size_t)L1 * Hd];
__device__ __nv_bfloat16 g_cth[(size_t)L2 * Hd];
__device__ __nv_bfloat16 g_ctl[(size_t)L2 * Hd];
__device__ __nv_bfloat16 g_aph[(size_t)NF * L3 * CAd];
__device__ __nv_bfloat16 g_apl[(size_t)NF * L3 * CAd];
__device__ __nv_bfloat16 g_Wh [6][(size_t)Hd * Hd];   // q,k,v,ki,vi,o
__device__ __nv_bfloat16 g_Wl [6][(size_t)Hd * Hd];
__device__ __nv_bfloat16 g_Wph[2][(size_t)Hd * CAd];  // kp,vp
__device__ __nv_bfloat16 g_Wpl[2][(size_t)Hd * CAd];
__device__ __nv_bfloat16 g_Ch [(size_t)L1 * Hd];
__device__ __nv_bfloat16 g_Cl [(size_t)L1 * Hd];

// bf16 hi/lo split attention operands
__device__ __nv_bfloat16 g_Qh [(size_t)L1 * Hd];
__device__ __nv_bfloat16 g_Ql [(size_t)L1 * Hd];
__device__ __nv_bfloat16 g_Kh [(size_t)LTXT * Hd];
__device__ __nv_bfloat16 g_Kl [(size_t)LTXT * Hd];
__device__ __nv_bfloat16 g_Vh [(size_t)LTXT * Hd];
__device__ __nv_bfloat16 g_Vl [(size_t)LTXT * Hd];
__device__ __nv_bfloat16 g_Kih[(size_t)IMG * Hd];
__device__ __nv_bfloat16 g_Kil[(size_t)IMG * Hd];
__device__ __nv_bfloat16 g_Vih[(size_t)IMG * Hd];
__device__ __nv_bfloat16 g_Vil[(size_t)IMG * Hd];
__device__ __nv_bfloat16 g_PKh[(size_t)NF * L3 * Hd];
__device__ __nv_bfloat16 g_PKl[(size_t)NF * L3 * Hd];
__device__ __nv_bfloat16 g_PVh[(size_t)NF * L3 * Hd];
__device__ __nv_bfloat16 g_PVl[(size_t)NF * L3 * Hd];

// ---------------------------------------------------------------------------
// Helpers
// ---------------------------------------------------------------------------
__device__ __forceinline__ unsigned pack_bf16(__nv_bfloat16 lo, __nv_bfloat16 hi)
{
    return ((unsigned)__bfloat16_as_ushort(hi) << 16) | (unsigned)__bfloat16_as_ushort(lo);
}

__device__ __forceinline__ void mma_bf16(float* d, const unsigned* a, const unsigned* b)
{
    asm volatile(
        "mma.sync.aligned.m16n8k16.row.col.f32.bf16.bf16.f32 "
        "{%0,%1,%2,%3}, {%4,%5,%6,%7}, {%8,%9}, {%0,%1,%2,%3};\n"
        : "+f"(d[0]), "+f"(d[1]), "+f"(d[2]), "+f"(d[3])
        : "r"(a[0]), "r"(a[1]), "r"(a[2]), "r"(a[3]), "r"(b[0]), "r"(b[1]));
}

__device__ __forceinline__ void ldsm_x4(unsigned* r, const void* p)
{
    unsigned addr = (unsigned)__cvta_generic_to_shared(p);
    asm volatile(
        "ldmatrix.sync.aligned.m8n8.x4.shared.b16 {%0,%1,%2,%3}, [%4];\n"
        : "=r"(r[0]), "=r"(r[1]), "=r"(r[2]), "=r"(r[3]) : "r"(addr));
}

__device__ __forceinline__ void ldsm_x4_t(unsigned* r, const void* p)
{
    unsigned addr = (unsigned)__cvta_generic_to_shared(p);
    asm volatile(
        "ldmatrix.sync.aligned.m8n8.x4.trans.shared.b16 {%0,%1,%2,%3}, [%4];\n"
        : "=r"(r[0]), "=r"(r[1]), "=r"(r[2]), "=r"(r[3]) : "r"(addr));
}

__device__ __forceinline__ void cp_async16(void* dst, const void* src, int szbytes)
{
    unsigned d = (unsigned)__cvta_generic_to_shared(dst);
    asm volatile("cp.async.cg.shared.global [%0], [%1], 16, %2;\n"
                 :: "r"(d), "l"(src), "r"(szbytes));
}

// split a pair of fp32 into bf16x2 hi and lo registers (a -> low half)
__device__ __forceinline__ void split_pack2(float a, float b, unsigned& hi, unsigned& lo)
{
    __nv_bfloat16 ha = __float2bfloat16_rn(a);
    __nv_bfloat16 hb = __float2bfloat16_rn(b);
    hi = pack_bf16(ha, hb);
    lo = pack_bf16(__float2bfloat16_rn(a - __bfloat162float(ha)),
                   __float2bfloat16_rn(b - __bfloat162float(hb)));
}

// ---------------------------------------------------------------------------
// Elementwise fp32 -> (hi, lo) bf16 split
// ---------------------------------------------------------------------------
__global__ __launch_bounds__(256) void split_kernel(
    const float4* __restrict__ src, uint2* __restrict__ hi,
    uint2* __restrict__ lo, int n4)
{
    int i = blockIdx.x * 256 + threadIdx.x;
    if (i >= n4) return;
    float4 a = src[i];
    unsigned h0, l0, h1, l1;
    split_pack2(a.x, a.y, h0, l0);
    split_pack2(a.z, a.w, h1, l1);
    hi[i] = make_uint2(h0, h1);
    lo[i] = make_uint2(l0, l1);
}

// ---------------------------------------------------------------------------
// RMSNorm over rows of length 1536 + hi/lo bf16 split output
// ---------------------------------------------------------------------------
__global__ __launch_bounds__(256) void rmsnorm_split(
    const float* __restrict__ X, const float* __restrict__ w,
    __nv_bfloat16* __restrict__ H, __nv_bfloat16* __restrict__ Lo)
{
    const int row = blockIdx.x;
    const float* x = X + (size_t)row * Hd;
    const int tid = threadIdx.x;

    float v[6];
    float ss = 0.f;
#pragma unroll
    for (int i = 0; i < 6; i++) {
        v[i] = x[tid + i * 256];
        ss = fmaf(v[i], v[i], ss);
    }
#pragma unroll
    for (int o = 16; o > 0; o >>= 1) ss += __shfl_xor_sync(0xffffffffu, ss, o);

    __shared__ float warp_s[8];
    __shared__ float s_scale;
    if ((tid & 31) == 0) warp_s[tid >> 5] = ss;
    __syncthreads();
    if (tid < 8) {
        float t = warp_s[tid];
#pragma unroll
        for (int o = 4; o > 0; o >>= 1) t += __shfl_xor_sync(0xffu, t, o);
        if (tid == 0) s_scale = rsqrtf(t * (1.f / (float)Hd) + EPSV);
    }
    __syncthreads();
    float sc = s_scale;
#pragma unroll
    for (int i = 0; i < 6; i++) {
        int c = tid + i * 256;
        float f = v[i] * sc * w[c];
        __nv_bfloat16 h = __float2bfloat16_rn(f);
        H[(size_t)row * Hd + c]  = h;
        Lo[(size_t)row * Hd + c] = __float2bfloat16_rn(f - __bfloat162float(h));
    }
}

// ---------------------------------------------------------------------------
// Pipelined tensor-core GEMM (bf16x3, pre-split operands) — unchanged from R4
// ---------------------------------------------------------------------------
#define GBM 128
#define GBN 128
#define GBK 16
#define TILE_E (GBM * GBK)

__device__ __forceinline__ int swz16(int r, int k)
{
    int chunk = (k >> 3) ^ ((r >> 2) & 1);
    return r * GBK + (chunk << 3) + (k & 7);
}

__global__ __launch_bounds__(256) void gemm_pipe(
    const __nv_bfloat16* __restrict__ Ah, const __nv_bfloat16* __restrict__ Al,
    const __nv_bfloat16* __restrict__ Bh, const __nv_bfloat16* __restrict__ Bl,
    const float* __restrict__ bias, float* __restrict__ C,
    int M, int Nn, int K)
{
    __shared__ __nv_bfloat16 s[2][4][TILE_E];

    const int tid  = threadIdx.x;
    const int warp = tid >> 5;
    const int lane = tid & 31;
    const int wm   = warp >> 1;
    const int wn   = warp & 1;
    const int bm   = blockIdx.y * GBM;
    const int bn   = blockIdx.x * GBN;

    const int lr   = tid >> 1;
    const int lc   = (tid & 1) << 3;
    const int loff = swz16(lr, lc);
    const bool va  = (bm + lr) < M;
    const int  ra  = va ? (bm + lr) : 0;
    const int  rb  = bn + lr;
    const int  sza = va ? 16 : 0;

    float acc[2][8][4];
#pragma unroll
    for (int i = 0; i < 2; i++)
#pragma unroll
        for (int j = 0; j < 8; j++)
#pragma unroll
            for (int t = 0; t < 4; t++) acc[i][j][t] = 0.f;

    const int nt = K / GBK;

    cp_async16(&s[0][0][loff], Ah + (size_t)ra * K + lc, sza);
    cp_async16(&s[0][1][loff], Al + (size_t)ra * K + lc, sza);
    cp_async16(&s[0][2][loff], Bh + (size_t)rb * K + lc, 16);
    cp_async16(&s[0][3][loff], Bl + (size_t)rb * K + lc, 16);
    asm volatile("cp.async.commit_group;\n" ::: "memory");

    const int rfrg = lane & 15;
    const int kf   = (lane >> 4) << 3;

    for (int t = 0; t < nt; t++) {
        if (t + 1 < nt) {
            const int st = (t + 1) & 1;
            const int k0 = (t + 1) * GBK;
            cp_async16(&s[st][0][loff], Ah + (size_t)ra * K + k0 + lc, sza);
            cp_async16(&s[st][1][loff], Al + (size_t)ra * K + k0 + lc, sza);
            cp_async16(&s[st][2][loff], Bh + (size_t)rb * K + k0 + lc, 16);
            cp_async16(&s[st][3][loff], Bl + (size_t)rb * K + k0 + lc, 16);
            asm volatile("cp.async.commit_group;\n" ::: "memory");
            asm volatile("cp.async.wait_group 1;\n" ::: "memory");
        } else {
            asm volatile("cp.async.wait_group 0;\n" ::: "memory");
        }
        __syncthreads();

        const __nv_bfloat16* pAh = s[t & 1][0];
        const __nv_bfloat16* pAl = s[t & 1][1];
        const __nv_bfloat16* pBh = s[t & 1][2];
        const __nv_bfloat16* pBl = s[t & 1][3];

        unsigned ah[2][4], al[2][4];
#pragma unroll
        for (int i = 0; i < 2; i++) {
            int r = wm * 32 + i * 16 + rfrg;
            ldsm_x4(ah[i], pAh + swz16(r, kf));
            ldsm_x4(al[i], pAl + swz16(r, kf));
        }

        unsigned bh[8][2], bl[8][2];
#pragma unroll
        for (int p = 0; p < 4; p++) {
            int n = wn * 64 + p * 16 + rfrg;
            unsigned tt[4];
            ldsm_x4(tt, pBh + swz16(n, kf));
            bh[p*2][0] = tt[0]; bh[p*2+1][0] = tt[1];
            bh[p*2][1] = tt[2]; bh[p*2+1][1] = tt[3];
            ldsm_x4(tt, pBl + swz16(n, kf));
            bl[p*2][0] = tt[0]; bl[p*2+1][0] = tt[1];
            bl[p*2][1] = tt[2]; bl[p*2+1][1] = tt[3];
        }

#pragma unroll
        for (int i = 0; i < 2; i++)
#pragma unroll
            for (int j = 0; j < 8; j++) {
                mma_bf16(acc[i][j], ah[i], bh[j]);
                mma_bf16(acc[i][j], ah[i], bl[j]);
                mma_bf16(acc[i][j], al[i], bh[j]);
            }
        __syncthreads();
    }

#pragma unroll
    for (int i = 0; i < 2; i++) {
        int r0 = bm + wm * 32 + i * 16 + (lane >> 2);
        int r1 = r0 + 8;
#pragma unroll
        for (int j = 0; j < 8; j++) {
            int c  = bn + wn * 64 + j * 8 + (lane & 3) * 2;
            float b0 = bias ? bias[c]     : 0.f;
            float b1 = bias ? bias[c + 1] : 0.f;
            if (r0 < M) {
                C[(size_t)r0 * Nn + c]     = acc[i][j][0] + b0;
                C[(size_t)r0 * Nn + c + 1] = acc[i][j][1] + b1;
            }
            if (r1 < M) {
                C[(size_t)r1 * Nn + c]     = acc[i][j][2] + b0;
                C[(size_t)r1 * Nn + c + 1] = acc[i][j][3] + b1;
            }
        }
    }
}

// ---------------------------------------------------------------------------
// Tensor-core fused 3-phase flash attention (bf16x3 for QK^T and P·V).
// grid = (L1/64, NH), block = 128 (4 warps x 16 query rows).
// Per-phase online softmax in m16n8 fragment layout; phases folded into a
// padded fp32 smem accumulator; output written as hi/lo bf16 split.
// ---------------------------------------------------------------------------
#define ATQ 64
#define ASTR 132                      // padded fp32 row stride for sO
#define ATTN_SMEM (64*128*2*2 + 32*128*2*4 + 64*ASTR*4)

// swizzled bf16 element offset in a [rows][128] tile; c8 = 16B-chunk (0..15)
__device__ __forceinline__ int soff(int r, int c8)
{
    return r * 128 + (((c8) ^ (r & 7)) << 3);
}

__global__ __launch_bounds__(128) void attn_mma(
    const __nv_bfloat16* __restrict__ Qh,  const __nv_bfloat16* __restrict__ Ql,
    const __nv_bfloat16* __restrict__ Kth, const __nv_bfloat16* __restrict__ Ktl,
    const __nv_bfloat16* __restrict__ Vth, const __nv_bfloat16* __restrict__ Vtl,
    const __nv_bfloat16* __restrict__ Kih, const __nv_bfloat16* __restrict__ Kil,
    const __nv_bfloat16* __restrict__ Vih, const __nv_bfloat16* __restrict__ Vil,
    const __nv_bfloat16* __restrict__ PKh, const __nv_bfloat16* __restrict__ PKl,
    const __nv_bfloat16* __restrict__ PVh, const __nv_bfloat16* __restrict__ PVl,
    const int* __restrict__ ctx_lens, const int* __restrict__ audio_lens,
    __nv_bfloat16* __restrict__ Ch, __nv_bfloat16* __restrict__ Cl)
{
    extern __shared__ char smraw[];
    __nv_bfloat16* sQh = (__nv_bfloat16*)smraw;
    __nv_bfloat16* sQl = sQh + 64 * 128;
    __nv_bfloat16* sKh = sQl + 64 * 128;
    __nv_bfloat16* sKl = sKh + 32 * 128;
    __nv_bfloat16* sVh = sKl + 32 * 128;
    __nv_bfloat16* sVl = sVh + 32 * 128;
    float*         sO  = (float*)(sVl + 32 * 128);

    const int head  = blockIdx.y;
    const int qbase = blockIdx.x * ATQ;
    const int tid   = threadIdx.x;
    const int warp  = tid >> 5;
    const int lane  = tid & 31;
    const int g     = lane >> 2;      // row-in-16 group
    const int tq    = lane & 3;       // quad thread
    const float scale = 0.08838834764831845f;  // 1/sqrt(128)

    // ---- load Q tile (64 x 128, hi+lo) into swizzled smem ----
#pragma unroll
    for (int i = 0; i < 8; i++) {
        int idx = tid + i * 128;              // 0..1023
        int r = idx >> 4, c8 = idx & 15;
        size_t go = (size_t)(qbase + r) * Hd + head * Dh + c8 * 8;
        int so = soff(r, c8);
        *(uint4*)&sQh[so] = *(const uint4*)&Qh[go];
        *(uint4*)&sQl[so] = *(const uint4*)&Ql[go];
    }
    // zero output accumulator
    for (int i = tid; i < 64 * ASTR; i += 128) sO[i] = 0.f;

    const int frame   = qbase >> 9;           // 512 queries per frame
    const int txt_len = ctx_lens[0];

    const int rfrg = lane & 15;
    const int chi  = lane >> 4;               // 16B-chunk select for ldmatrix

    for (int phase = 0; phase < 3; phase++) {
        const __nv_bfloat16 *KH, *KL, *VH, *VL;
        int klen;
        if (phase == 0)      { KH = Kih; KL = Kil; VH = Vih; VL = Vil; klen = IMG; }
        else if (phase == 1) { KH = Kth; KL = Ktl; VH = Vth; VL = Vtl; klen = txt_len; }
        else {
            size_t fo = (size_t)frame * L3 * Hd;
            KH = PKh + fo; KL = PKl + fo; VH = PVh + fo; VL = PVl + fo;
            klen = audio_lens[frame];
        }

        float m0 = -1e30f, m1 = -1e30f, l0 = 0.f, l1 = 0.f;
        float o[16][4];
#pragma unroll
        for (int n = 0; n < 16; n++)
#pragma unroll
            for (int e = 0; e < 4; e++) o[n][e] = 0.f;

        for (int kb = 0; kb < klen; kb += 32) {
            const int cl = min(32, klen - kb);

            __syncthreads();
            // ---- load K/V chunk (32 x 128 hi+lo each) ----
#pragma unroll
            for (int i = 0; i < 4; i++) {
                int idx = tid + i * 128;      // 0..511
                int r = idx >> 4, c8 = idx & 15;
                if (r < cl) {
                    size_t go = (size_t)(kb + r) * Hd + head * Dh + c8 * 8;
                    int so = soff(r, c8);
                    *(uint4*)&sKh[so] = *(const uint4*)&KH[go];
                    *(uint4*)&sKl[so] = *(const uint4*)&KL[go];
                    *(uint4*)&sVh[so] = *(const uint4*)&VH[go];
                    *(uint4*)&sVl[so] = *(const uint4*)&VL[go];
                }
            }
            __syncthreads();

            // ---- S = Q K^T (bf16x3), 64x32 per block, 16x32 per warp ----
            float sacc[4][4];
#pragma unroll
            for (int n = 0; n < 4; n++)
#pragma unroll
                for (int e = 0; e < 4; e++) sacc[n][e] = 0.f;

#pragma unroll
            for (int ks = 0; ks < 8; ks++) {
                const int c8 = ks * 2 + chi;
                unsigned aqh[4], aql[4];
                ldsm_x4(aqh, &sQh[soff(warp * 16 + rfrg, c8)]);
                ldsm_x4(aql, &sQl[soff(warp * 16 + rfrg, c8)]);

                unsigned kbh[4][2], kbl[4][2];
#pragma unroll
                for (int p = 0; p < 2; p++) {
                    unsigned t[4];
                    ldsm_x4(t, &sKh[soff(p * 16 + rfrg, c8)]);
                    kbh[p*2][0] = t[0]; kbh[p*2+1][0] = t[1];
                    kbh[p*2][1] = t[2]; kbh[p*2+1][1] = t[3];
                    ldsm_x4(t, &sKl[soff(p * 16 + rfrg, c8)]);
                    kbl[p*2][0] = t[0]; kbl[p*2+1][0] = t[1];
                    kbl[p*2][1] = t[2]; kbl[p*2+1][1] = t[3];
                }
#pragma unroll
                for (int n = 0; n < 4; n++) {
                    mma_bf16(sacc[n], aqh, kbh[n]);
                    mma_bf16(sacc[n], aqh, kbl[n]);
                    mma_bf16(sacc[n], aql, kbh[n]);
                }
            }

            // ---- online softmax in fragment layout ----
            float sv[4][4];
            float rmax0 = -1e30f, rmax1 = -1e30f;
#pragma unroll
            for (int n = 0; n < 4; n++) {
                int colb = kb + n * 8 + tq * 2;
                bool v0 = colb < klen, v1 = (colb + 1) < klen;
                float x0 = v0 ? sacc[n][0] * scale : -1e30f;
                float x1 = v1 ? sacc[n][1] * scale : -1e30f;
                float x2 = v0 ? sacc[n][2] * scale : -1e30f;
                float x3 = v1 ? sacc[n][3] * scale : -1e30f;
                sv[n][0] = x0; sv[n][1] = x1; sv[n][2] = x2; sv[n][3] = x3;
                rmax0 = fmaxf(rmax0, fmaxf(x0, x1));
                rmax1 = fmaxf(rmax1, fmaxf(x2, x3));
            }
            rmax0 = fmaxf(rmax0, __shfl_xor_sync(0xffffffffu, rmax0, 1));
            rmax0 = fmaxf(rmax0, __shfl_xor_sync(0xffffffffu, rmax0, 2));
            rmax1 = fmaxf(rmax1, __shfl_xor_sync(0xffffffffu, rmax1, 1));
            rmax1 = fmaxf(rmax1, __shfl_xor_sync(0xffffffffu, rmax1, 2));

            float mn0 = fmaxf(m0, rmax0), mn1 = fmaxf(m1, rmax1);
            float c0 = __expf(m0 - mn0),  c1 = __expf(m1 - mn1);
            float s0 = 0.f, s1 = 0.f;
#pragma unroll
            for (int n = 0; n < 4; n++) {
                float p0 = __expf(sv[n][0] - mn0);
                float p1 = __expf(sv[n][1] - mn0);
                float p2 = __expf(sv[n][2] - mn1);
                float p3 = __expf(sv[n][3] - mn1);
                sv[n][0] = p0; sv[n][1] = p1; sv[n][2] = p2; sv[n][3] = p3;
                s0 += p0 + p1; s1 += p2 + p3;
            }
            s0 += __shfl_xor_sync(0xffffffffu, s0, 1);
            s0 += __shfl_xor_sync(0xffffffffu, s0, 2);
            s1 += __shfl_xor_sync(0xffffffffu, s1, 1);
            s1 += __shfl_xor_sync(0xffffffffu, s1, 2);
            l0 = l0 * c0 + s0; l1 = l1 * c1 + s1;
            m0 = mn0; m1 = mn1;

#pragma unroll
            for (int n = 0; n < 16; n++) {
                o[n][0] *= c0; o[n][1] *= c0;
                o[n][2] *= c1; o[n][3] *= c1;
            }

            // ---- P fragments (A-operand layout == C layout), hi/lo split ----
            unsigned aPh[2][4], aPl[2][4];
#pragma unroll
            for (int ks = 0; ks < 2; ks++) {
                split_pack2(sv[2*ks][0],   sv[2*ks][1],   aPh[ks][0], aPl[ks][0]);
                split_pack2(sv[2*ks][2],   sv[2*ks][3],   aPh[ks][1], aPl[ks][1]);
                split_pack2(sv[2*ks+1][0], sv[2*ks+1][1], aPh[ks][2], aPl[ks][2]);
                split_pack2(sv[2*ks+1][2], sv[2*ks+1][3], aPh[ks][3], aPl[ks][3]);
            }

            // ---- O += P V (bf16x3), V via ldmatrix.trans ----
#pragma unroll
            for (int ks = 0; ks < 2; ks++) {
#pragma unroll
                for (int ntp = 0; ntp < 8; ntp++) {
                    // rows = keys, cols = d; trans load of k16 x n16
                    int vr = ks * 16 + ((lane >> 3) & 1) * 8 + (lane & 7);
                    int vc = ntp * 2 + (lane >> 4);
                    unsigned th[4], tl[4];
                    ldsm_x4_t(th, &sVh[soff(vr, vc)]);
                    ldsm_x4_t(tl, &sVl[soff(vr, vc)]);
                    unsigned bh0[2] = {th[0], th[1]};
                    unsigned bh1[2] = {th[2], th[3]};
                    unsigned bl0[2] = {tl[0], tl[1]};
                    unsigned bl1[2] = {tl[2], tl[3]};
                    mma_bf16(o[2*ntp],   aPh[ks], bh0);
                    mma_bf16(o[2*ntp],   aPh[ks], bl0);
                    mma_bf16(o[2*ntp],   aPl[ks], bh0);
                    mma_bf16(o[2*ntp+1], aPh[ks], bh1);
                    mma_bf16(o[2*ntp+1], aPh[ks], bl1);
                    mma_bf16(o[2*ntp+1], aPl[ks], bh1);
                }
            }
        } // kb

        // ---- fold normalized phase result into sO (disjoint rows per warp) ----
        float rl0 = 1.f / l0, rl1 = 1.f / l1;
        int row0 = warp * 16 + g;
#pragma unroll
        for (int n = 0; n < 16; n++) {
            int col = n * 8 + tq * 2;
            sO[row0 * ASTR + col]           += o[n][0] * rl0;
            sO[row0 * ASTR + col + 1]       += o[n][1] * rl0;
            sO[(row0 + 8) * ASTR + col]     += o[n][2] * rl1;
            sO[(row0 + 8) * ASTR + col + 1] += o[n][3] * rl1;
        }
    } // phase

    __syncthreads();
    // ---- write combined output as hi/lo bf16 ----
#pragma unroll
    for (int i = 0; i < 16; i++) {
        int idx = tid + i * 128;              // 0..2047
        int r = idx >> 5, cb = (idx & 31) * 4;
        float f0 = sO[r * ASTR + cb + 0];
        float f1 = sO[r * ASTR + cb + 1];
        float f2 = sO[r * ASTR + cb + 2];
        float f3 = sO[r * ASTR + cb + 3];
        unsigned h0, l0u, h1, l1u;
        split_pack2(f0, f1, h0, l0u);
        split_pack2(f2, f3, h1, l1u);
        size_t go = (size_t)(qbase + r) * Hd + head * Dh + cb;
        *(uint2*)&Ch[go] = make_uint2(h0, h1);
        *(uint2*)&Cl[go] = make_uint2(l0u, l1u);
    }
}

// ---------------------------------------------------------------------------
// Launch
// ---------------------------------------------------------------------------
static void run_split(const float* src, __nv_bfloat16* hi, __nv_bfloat16* lo, size_t n)
{
    int n4 = (int)(n / 4);
    split_kernel<<<(n4 + 255) / 256, 256>>>(
        (const float4*)src, (uint2*)hi, (uint2*)lo, n4);
}

extern "C" void kernel_launch(void* const* d_in, const int* in_sizes, int n_in,
                              void* d_out, int out_size)
{
    const float* x          = (const float*)d_in[0];
    const float* context    = (const float*)d_in[1];
    const float* audio_proj = (const float*)d_in[2];
    const float* Wq  = (const float*)d_in[3];
    const float* bq  = (const float*)d_in[4];
    const float* Wk  = (const float*)d_in[5];
    const float* bk  = (const float*)d_in[6];
    const float* Wv  = (const float*)d_in[7];
    const float* bv  = (const float*)d_in[8];
    const float* Wki = (const float*)d_in[9];
    const float* bki = (const float*)d_in[10];
    const float* Wvi = (const float*)d_in[11];
    const float* bvi = (const float*)d_in[12];
    const float* Wo  = (const float*)d_in[13];
    const float* bo  = (const float*)d_in[14];
    const float* nq  = (const float*)d_in[15];
    const float* nk  = (const float*)d_in[16];
    const float* nki = (const float*)d_in[17];
    const float* Wkp = (const float*)d_in[18];
    const float* Wvp = (const float*)d_in[19];
    const int* ctx_lens   = (const int*)d_in[20];
    const int* audio_lens = (const int*)d_in[21];
    float* out = (float*)d_out;

    float *gQ, *gK, *gV, *gKi, *gVi, *gIPK, *gIPV;
    cudaGetSymbolAddress((void**)&gQ,   g_Q);
    cudaGetSymbolAddress((void**)&gK,   g_K);
    cudaGetSymbolAddress((void**)&gV,   g_V);
    cudaGetSymbolAddress((void**)&gKi,  g_Kimg);
    cudaGetSymbolAddress((void**)&gVi,  g_Vimg);
    cudaGetSymbolAddress((void**)&gIPK, g_IPK);
    cudaGetSymbolAddress((void**)&gIPV, g_IPV);

    __nv_bfloat16 *xh, *xl, *cth, *ctl, *aph, *apl, *Wh, *Wl, *Wph, *Wpl, *Chh, *Cll;
    cudaGetSymbolAddress((void**)&xh,  g_xh);
    cudaGetSymbolAddress((void**)&xl,  g_xl);
    cudaGetSymbolAddress((void**)&cth, g_cth);
    cudaGetSymbolAddress((void**)&ctl, g_ctl);
    cudaGetSymbolAddress((void**)&aph, g_aph);
    cudaGetSymbolAddress((void**)&apl, g_apl);
    cudaGetSymbolAddress((void**)&Wh,  g_Wh);
    cudaGetSymbolAddress((void**)&Wl,  g_Wl);
    cudaGetSymbolAddress((void**)&Wph, g_Wph);
    cudaGetSymbolAddress((void**)&Wpl, g_Wpl);
    cudaGetSymbolAddress((void**)&Chh, g_Ch);
    cudaGetSymbolAddress((void**)&Cll, g_Cl);

    __nv_bfloat16 *Qh, *Ql, *Kh, *Kl, *Vh, *Vl, *Kih, *Kil, *Vih, *Vil,
                  *PKh, *PKl, *PVh, *PVl;
    cudaGetSymbolAddress((void**)&Qh,  g_Qh);
    cudaGetSymbolAddress((void**)&Ql,  g_Ql);
    cudaGetSymbolAddress((void**)&Kh,  g_Kh);
    cudaGetSymbolAddress((void**)&Kl,  g_Kl);
    cudaGetSymbolAddress((void**)&Vh,  g_Vh);
    cudaGetSymbolAddress((void**)&Vl,  g_Vl);
    cudaGetSymbolAddress((void**)&Kih, g_Kih);
    cudaGetSymbolAddress((void**)&Kil, g_Kil);
    cudaGetSymbolAddress((void**)&Vih, g_Vih);
    cudaGetSymbolAddress((void**)&Vil, g_Vil);
    cudaGetSymbolAddress((void**)&PKh, g_PKh);
    cudaGetSymbolAddress((void**)&PKl, g_PKl);
    cudaGetSymbolAddress((void**)&PVh, g_PVh);
    cudaGetSymbolAddress((void**)&PVl, g_PVl);

    cudaFuncSetAttribute(attn_mma, cudaFuncAttributeMaxDynamicSharedMemorySize,
                         ATTN_SMEM);

    const size_t WSZ  = (size_t)Hd * Hd;
    const size_t WPSZ = (size_t)Hd * CAd;

    // ---- split GEMM inputs ----
    run_split(x,          xh,  xl,  (size_t)L1 * Hd);
    run_split(context,    cth, ctl, (size_t)L2 * Hd);
    run_split(audio_proj, aph, apl, (size_t)NF * L3 * CAd);
    run_split(Wq,  Wh + 0 * WSZ, Wl + 0 * WSZ, WSZ);
    run_split(Wk,  Wh + 1 * WSZ, Wl + 1 * WSZ, WSZ);
    run_split(Wv,  Wh + 2 * WSZ, Wl + 2 * WSZ, WSZ);
    run_split(Wki, Wh + 3 * WSZ, Wl + 3 * WSZ, WSZ);
    run_split(Wvi, Wh + 4 * WSZ, Wl + 4 * WSZ, WSZ);
    run_split(Wo,  Wh + 5 * WSZ, Wl + 5 * WSZ, WSZ);
    run_split(Wkp, Wph + 0 * WPSZ, Wpl + 0 * WPSZ, WPSZ);
    run_split(Wvp, Wph + 1 * WPSZ, Wpl + 1 * WPSZ, WPSZ);

    const __nv_bfloat16* ctxth = cth + (size_t)IMG * Hd;
    const __nv_bfloat16* ctxtl = ctl + (size_t)IMG * Hd;

    // ---- projections (fp32 out) + norm/split to bf16 hi/lo ----
    gemm_pipe<<<dim3(Hd / GBN, L1 / GBM), 256>>>(
        xh, xl, Wh + 0 * WSZ, Wl + 0 * WSZ, bq, gQ, L1, Hd, Hd);
    rmsnorm_split<<<L1, 256>>>(gQ, nq, Qh, Ql);

    gemm_pipe<<<dim3(Hd / GBN, LTXT / GBM), 256>>>(
        ctxth, ctxtl, Wh + 1 * WSZ, Wl + 1 * WSZ, bk, gK, LTXT, Hd, Hd);
    rmsnorm_split<<<LTXT, 256>>>(gK, nk, Kh, Kl);
    gemm_pipe<<<dim3(Hd / GBN, LTXT / GBM), 256>>>(
        ctxth, ctxtl, Wh + 2 * WSZ, Wl + 2 * WSZ, bv, gV, LTXT, Hd, Hd);
    run_split(gV, Vh, Vl, (size_t)LTXT * Hd);

    gemm_pipe<<<dim3(Hd / GBN, (IMG + GBM - 1) / GBM), 256>>>(
        cth, ctl, Wh + 3 * WSZ, Wl + 3 * WSZ, bki, gKi, IMG, Hd, Hd);
    rmsnorm_split<<<IMG, 256>>>(gKi, nki, Kih, Kil);
    gemm_pipe<<<dim3(Hd / GBN, (IMG + GBM - 1) / GBM), 256>>>(
        cth, ctl, Wh + 4 * WSZ, Wl + 4 * WSZ, bvi, gVi, IMG, Hd, Hd);
    run_split(gVi, Vih, Vil, (size_t)IMG * Hd);

    const int AM = NF * L3;   // 672 audio rows
    gemm_pipe<<<dim3(Hd / GBN, (AM + GBM - 1) / GBM), 256>>>(
        aph, apl, Wph + 0 * WPSZ, Wpl + 0 * WPSZ, nullptr, gIPK, AM, Hd, CAd);
    run_split(gIPK, PKh, PKl, (size_t)AM * Hd);
    gemm_pipe<<<dim3(Hd / GBN, (AM + GBM - 1) / GBM), 256>>>(
        aph, apl, Wph + 1 * WPSZ, Wpl + 1 * WPSZ, nullptr, gIPV, AM, Hd, CAd);
    run_split(gIPV, PVh, PVl, (size_t)AM * Hd);

    // ---- tensor-core fused attention -> bf16 hi/lo combined ----
    attn_mma<<<dim3(L1 / ATQ, NH), 128, ATTN_SMEM>>>(
        Qh, Ql, Kh, Kl, Vh, Vl, Kih, Kil, Vih, Vil, PKh, PKl, PVh, PVl,
        ctx_lens, audio_lens, Chh, Cll);

    // ---- output projection ----
    gemm_pipe<<<dim3(Hd / GBN, L1 / GBM), 256>>>(
        Chh, Cll, Wh + 5 * WSZ, Wl + 5 * WSZ, bo, out, L1, Hd, Hd);
}

// round 10
// speedup vs baseline: 7.0000x; 1.1722x over previous
#include <cuda_runtime.h>
#include <cuda_bf16.h>
#include <math.h>

// ---------------------------------------------------------------------------
// Problem constants
// ---------------------------------------------------------------------------
#define L1   10752
#define NF   21
#define L2   769
#define IMG  257
#define LTXT 512          // L2 - IMG
#define Hd   1536
#define NH   12
#define Dh   128
#define L3   32
#define CAd  768
#define EPSV 1e-6f

// ---------------------------------------------------------------------------
// Scratch (static __device__ globals — allocation-free per harness rules)
// ---------------------------------------------------------------------------
__device__ float g_Q   [(size_t)L1 * Hd];
__device__ float g_K   [(size_t)LTXT * Hd];
__device__ float g_Kimg[(size_t)IMG * Hd];

// bf16 hi/lo split operands for GEMMs
__device__ __nv_bfloat16 g_xh [(size_t)L1 * Hd];
__device__ __nv_bfloat16 g_xl [(size_t)L1 * Hd];
__device__ __nv_bfloat16 g_cth[(size_t)L2 * Hd];
__device__ __nv_bfloat16 g_ctl[(size_t)L2 * Hd];
__device__ __nv_bfloat16 g_aph[(size_t)NF * L3 * CAd];
__device__ __nv_bfloat16 g_apl[(size_t)NF * L3 * CAd];
__device__ __nv_bfloat16 g_Wh [6][(size_t)Hd * Hd];   // q,k,v,ki,vi,o
__device__ __nv_bfloat16 g_Wl [6][(size_t)Hd * Hd];
__device__ __nv_bfloat16 g_Wph[2][(size_t)Hd * CAd];  // kp,vp
__device__ __nv_bfloat16 g_Wpl[2][(size_t)Hd * CAd];
__device__ __nv_bfloat16 g_Ch [(size_t)L1 * Hd];
__device__ __nv_bfloat16 g_Cl [(size_t)L1 * Hd];

// bf16 hi/lo split attention operands
__device__ __nv_bfloat16 g_Qh [(size_t)L1 * Hd];
__device__ __nv_bfloat16 g_Ql [(size_t)L1 * Hd];
__device__ __nv_bfloat16 g_Kh [(size_t)LTXT * Hd];
__device__ __nv_bfloat16 g_Kl [(size_t)LTXT * Hd];
__device__ __nv_bfloat16 g_Vh [(size_t)LTXT * Hd];
__device__ __nv_bfloat16 g_Vl [(size_t)LTXT * Hd];
__device__ __nv_bfloat16 g_Kih[(size_t)IMG * Hd];
__device__ __nv_bfloat16 g_Kil[(size_t)IMG * Hd];
__device__ __nv_bfloat16 g_Vih[(size_t)IMG * Hd];
__device__ __nv_bfloat16 g_Vil[(size_t)IMG * Hd];
__device__ __nv_bfloat16 g_PKh[(size_t)NF * L3 * Hd];
__device__ __nv_bfloat16 g_PKl[(size_t)NF * L3 * Hd];
__device__ __nv_bfloat16 g_PVh[(size_t)NF * L3 * Hd];
__device__ __nv_bfloat16 g_PVl[(size_t)NF * L3 * Hd];

// ---------------------------------------------------------------------------
// Helpers
// ---------------------------------------------------------------------------
__device__ __forceinline__ unsigned pack_bf16(__nv_bfloat16 lo, __nv_bfloat16 hi)
{
    return ((unsigned)__bfloat16_as_ushort(hi) << 16) | (unsigned)__bfloat16_as_ushort(lo);
}

__device__ __forceinline__ void mma_bf16(float* d, const unsigned* a, const unsigned* b)
{
    asm volatile(
        "mma.sync.aligned.m16n8k16.row.col.f32.bf16.bf16.f32 "
        "{%0,%1,%2,%3}, {%4,%5,%6,%7}, {%8,%9}, {%0,%1,%2,%3};\n"
        : "+f"(d[0]), "+f"(d[1]), "+f"(d[2]), "+f"(d[3])
        : "r"(a[0]), "r"(a[1]), "r"(a[2]), "r"(a[3]), "r"(b[0]), "r"(b[1]));
}

__device__ __forceinline__ void ldsm_x4(unsigned* r, const void* p)
{
    unsigned addr = (unsigned)__cvta_generic_to_shared(p);
    asm volatile(
        "ldmatrix.sync.aligned.m8n8.x4.shared.b16 {%0,%1,%2,%3}, [%4];\n"
        : "=r"(r[0]), "=r"(r[1]), "=r"(r[2]), "=r"(r[3]) : "r"(addr));
}

__device__ __forceinline__ void ldsm_x4_t(unsigned* r, const void* p)
{
    unsigned addr = (unsigned)__cvta_generic_to_shared(p);
    asm volatile(
        "ldmatrix.sync.aligned.m8n8.x4.trans.shared.b16 {%0,%1,%2,%3}, [%4];\n"
        : "=r"(r[0]), "=r"(r[1]), "=r"(r[2]), "=r"(r[3]) : "r"(addr));
}

__device__ __forceinline__ void cp_async16(void* dst, const void* src, int szbytes)
{
    unsigned d = (unsigned)__cvta_generic_to_shared(dst);
    asm volatile("cp.async.cg.shared.global [%0], [%1], 16, %2;\n"
                 :: "r"(d), "l"(src), "r"(szbytes));
}

__device__ __forceinline__ void split_pack2(float a, float b, unsigned& hi, unsigned& lo)
{
    __nv_bfloat16 ha = __float2bfloat16_rn(a);
    __nv_bfloat16 hb = __float2bfloat16_rn(b);
    hi = pack_bf16(ha, hb);
    lo = pack_bf16(__float2bfloat16_rn(a - __bfloat162float(ha)),
                   __float2bfloat16_rn(b - __bfloat162float(hb)));
}

// ---------------------------------------------------------------------------
// Elementwise fp32 -> (hi, lo) bf16 split
// ---------------------------------------------------------------------------
__global__ __launch_bounds__(256) void split_kernel(
    const float4* __restrict__ src, uint2* __restrict__ hi,
    uint2* __restrict__ lo, int n4)
{
    int i = blockIdx.x * 256 + threadIdx.x;
    if (i >= n4) return;
    float4 a = src[i];
    unsigned h0, l0, h1, l1;
    split_pack2(a.x, a.y, h0, l0);
    split_pack2(a.z, a.w, h1, l1);
    hi[i] = make_uint2(h0, h1);
    lo[i] = make_uint2(l0, l1);
}

// ---------------------------------------------------------------------------
// RMSNorm over rows of length 1536 + hi/lo bf16 split output
// ---------------------------------------------------------------------------
__global__ __launch_bounds__(256) void rmsnorm_split(
    const float* __restrict__ X, const float* __restrict__ w,
    __nv_bfloat16* __restrict__ H, __nv_bfloat16* __restrict__ Lo)
{
    const int row = blockIdx.x;
    const float* x = X + (size_t)row * Hd;
    const int tid = threadIdx.x;

    float v[6];
    float ss = 0.f;
#pragma unroll
    for (int i = 0; i < 6; i++) {
        v[i] = x[tid + i * 256];
        ss = fmaf(v[i], v[i], ss);
    }
#pragma unroll
    for (int o = 16; o > 0; o >>= 1) ss += __shfl_xor_sync(0xffffffffu, ss, o);

    __shared__ float warp_s[8];
    __shared__ float s_scale;
    if ((tid & 31) == 0) warp_s[tid >> 5] = ss;
    __syncthreads();
    if (tid < 8) {
        float t = warp_s[tid];
#pragma unroll
        for (int o = 4; o > 0; o >>= 1) t += __shfl_xor_sync(0xffu, t, o);
        if (tid == 0) s_scale = rsqrtf(t * (1.f / (float)Hd) + EPSV);
    }
    __syncthreads();
    float sc = s_scale;
#pragma unroll
    for (int i = 0; i < 6; i++) {
        int c = tid + i * 256;
        float f = v[i] * sc * w[c];
        __nv_bfloat16 h = __float2bfloat16_rn(f);
        H[(size_t)row * Hd + c]  = h;
        Lo[(size_t)row * Hd + c] = __float2bfloat16_rn(f - __bfloat162float(h));
    }
}

// ---------------------------------------------------------------------------
// Pipelined tensor-core GEMM (bf16x3, pre-split operands)
// ---------------------------------------------------------------------------
#define GBM 128
#define GBN 128
#define GBK 16
#define TILE_E (GBM * GBK)

__device__ __forceinline__ int swz16(int r, int k)
{
    int chunk = (k >> 3) ^ ((r >> 2) & 1);
    return r * GBK + (chunk << 3) + (k & 7);
}

// Core GEMM body shared by both epilogue variants via inline function.
struct GemmAcc { float a[2][8][4]; };

__device__ __forceinline__ void gemm_body(
    const __nv_bfloat16* __restrict__ Ah, const __nv_bfloat16* __restrict__ Al,
    const __nv_bfloat16* __restrict__ Bh, const __nv_bfloat16* __restrict__ Bl,
    int M, int K, int bm, int bn, GemmAcc& acc,
    __nv_bfloat16 (*s)[4][TILE_E])
{
    const int tid  = threadIdx.x;
    const int warp = tid >> 5;
    const int lane = tid & 31;
    const int wm   = warp >> 1;
    const int wn   = warp & 1;

    const int lr   = tid >> 1;
    const int lc   = (tid & 1) << 3;
    const int loff = swz16(lr, lc);
    const bool va  = (bm + lr) < M;
    const int  ra  = va ? (bm + lr) : 0;
    const int  rb  = bn + lr;
    const int  sza = va ? 16 : 0;

#pragma unroll
    for (int i = 0; i < 2; i++)
#pragma unroll
        for (int j = 0; j < 8; j++)
#pragma unroll
            for (int t = 0; t < 4; t++) acc.a[i][j][t] = 0.f;

    const int nt = K / GBK;

    cp_async16(&s[0][0][loff], Ah + (size_t)ra * K + lc, sza);
    cp_async16(&s[0][1][loff], Al + (size_t)ra * K + lc, sza);
    cp_async16(&s[0][2][loff], Bh + (size_t)rb * K + lc, 16);
    cp_async16(&s[0][3][loff], Bl + (size_t)rb * K + lc, 16);
    asm volatile("cp.async.commit_group;\n" ::: "memory");

    const int rfrg = lane & 15;
    const int kf   = (lane >> 4) << 3;

    for (int t = 0; t < nt; t++) {
        if (t + 1 < nt) {
            const int st = (t + 1) & 1;
            const int k0 = (t + 1) * GBK;
            cp_async16(&s[st][0][loff], Ah + (size_t)ra * K + k0 + lc, sza);
            cp_async16(&s[st][1][loff], Al + (size_t)ra * K + k0 + lc, sza);
            cp_async16(&s[st][2][loff], Bh + (size_t)rb * K + k0 + lc, 16);
            cp_async16(&s[st][3][loff], Bl + (size_t)rb * K + k0 + lc, 16);
            asm volatile("cp.async.commit_group;\n" ::: "memory");
            asm volatile("cp.async.wait_group 1;\n" ::: "memory");
        } else {
            asm volatile("cp.async.wait_group 0;\n" ::: "memory");
        }
        __syncthreads();

        const __nv_bfloat16* pAh = s[t & 1][0];
        const __nv_bfloat16* pAl = s[t & 1][1];
        const __nv_bfloat16* pBh = s[t & 1][2];
        const __nv_bfloat16* pBl = s[t & 1][3];

        unsigned ah[2][4], al[2][4];
#pragma unroll
        for (int i = 0; i < 2; i++) {
            int r = wm * 32 + i * 16 + rfrg;
            ldsm_x4(ah[i], pAh + swz16(r, kf));
            ldsm_x4(al[i], pAl + swz16(r, kf));
        }

        unsigned bh[8][2], bl[8][2];
#pragma unroll
        for (int p = 0; p < 4; p++) {
            int n = wn * 64 + p * 16 + rfrg;
            unsigned tt[4];
            ldsm_x4(tt, pBh + swz16(n, kf));
            bh[p*2][0] = tt[0]; bh[p*2+1][0] = tt[1];
            bh[p*2][1] = tt[2]; bh[p*2+1][1] = tt[3];
            ldsm_x4(tt, pBl + swz16(n, kf));
            bl[p*2][0] = tt[0]; bl[p*2+1][0] = tt[1];
            bl[p*2][1] = tt[2]; bl[p*2+1][1] = tt[3];
        }

#pragma unroll
        for (int i = 0; i < 2; i++)
#pragma unroll
            for (int j = 0; j < 8; j++) {
                mma_bf16(acc.a[i][j], ah[i], bh[j]);
                mma_bf16(acc.a[i][j], ah[i], bl[j]);
                mma_bf16(acc.a[i][j], al[i], bh[j]);
            }
        __syncthreads();
    }
}

__global__ __launch_bounds__(256) void gemm_pipe(
    const __nv_bfloat16* __restrict__ Ah, const __nv_bfloat16* __restrict__ Al,
    const __nv_bfloat16* __restrict__ Bh, const __nv_bfloat16* __restrict__ Bl,
    const float* __restrict__ bias, float* __restrict__ C,
    int M, int Nn, int K)
{
    __shared__ __nv_bfloat16 s[2][4][TILE_E];
    const int bm = blockIdx.y * GBM;
    const int bn = blockIdx.x * GBN;

    GemmAcc acc;
    gemm_body(Ah, Al, Bh, Bl, M, K, bm, bn, acc, s);

    const int lane = threadIdx.x & 31;
    const int warp = threadIdx.x >> 5;
    const int wm = warp >> 1, wn = warp & 1;

#pragma unroll
    for (int i = 0; i < 2; i++) {
        int r0 = bm + wm * 32 + i * 16 + (lane >> 2);
        int r1 = r0 + 8;
#pragma unroll
        for (int j = 0; j < 8; j++) {
            int c  = bn + wn * 64 + j * 8 + (lane & 3) * 2;
            float b0 = bias ? bias[c]     : 0.f;
            float b1 = bias ? bias[c + 1] : 0.f;
            if (r0 < M) {
                C[(size_t)r0 * Nn + c]     = acc.a[i][j][0] + b0;
                C[(size_t)r0 * Nn + c + 1] = acc.a[i][j][1] + b1;
            }
            if (r1 < M) {
                C[(size_t)r1 * Nn + c]     = acc.a[i][j][2] + b0;
                C[(size_t)r1 * Nn + c + 1] = acc.a[i][j][3] + b1;
            }
        }
    }
}

// Dual GEMM: two weight matrices share one A; per-half epilogue writes either
// fp32 (for later rmsnorm) or hi/lo bf16 split.
__global__ __launch_bounds__(256) void gemm_dual(
    const __nv_bfloat16* __restrict__ Ah, const __nv_bfloat16* __restrict__ Al,
    const __nv_bfloat16* __restrict__ W1h, const __nv_bfloat16* __restrict__ W1l,
    const float* __restrict__ b1, float* __restrict__ C1f,
    __nv_bfloat16* __restrict__ C1h, __nv_bfloat16* __restrict__ C1l,
    const __nv_bfloat16* __restrict__ W2h, const __nv_bfloat16* __restrict__ W2l,
    const float* __restrict__ b2, float* __restrict__ C2f,
    __nv_bfloat16* __restrict__ C2h, __nv_bfloat16* __restrict__ C2l,
    int M, int Nn, int K)
{
    __shared__ __nv_bfloat16 s[2][4][TILE_E];
    const int nbx  = Nn / GBN;
    const int half = blockIdx.x / nbx;
    const int bn   = (blockIdx.x % nbx) * GBN;
    const int bm   = blockIdx.y * GBM;

    const __nv_bfloat16* Bh = half ? W2h : W1h;
    const __nv_bfloat16* Bl = half ? W2l : W1l;
    const float* bias = half ? b2 : b1;
    float* Cf = half ? C2f : C1f;
    __nv_bfloat16* Chp = half ? C2h : C1h;
    __nv_bfloat16* Clp = half ? C2l : C1l;

    GemmAcc acc;
    gemm_body(Ah, Al, Bh, Bl, M, K, bm, bn, acc, s);

    const int lane = threadIdx.x & 31;
    const int warp = threadIdx.x >> 5;
    const int wm = warp >> 1, wn = warp & 1;

#pragma unroll
    for (int i = 0; i < 2; i++) {
        int r0 = bm + wm * 32 + i * 16 + (lane >> 2);
        int r1 = r0 + 8;
#pragma unroll
        for (int j = 0; j < 8; j++) {
            int c  = bn + wn * 64 + j * 8 + (lane & 3) * 2;
            float b0 = bias ? bias[c]     : 0.f;
            float b1v = bias ? bias[c + 1] : 0.f;
            float v0 = acc.a[i][j][0] + b0, v1 = acc.a[i][j][1] + b1v;
            float v2 = acc.a[i][j][2] + b0, v3 = acc.a[i][j][3] + b1v;
            if (Cf) {
                if (r0 < M) {
                    Cf[(size_t)r0 * Nn + c]     = v0;
                    Cf[(size_t)r0 * Nn + c + 1] = v1;
                }
                if (r1 < M) {
                    Cf[(size_t)r1 * Nn + c]     = v2;
                    Cf[(size_t)r1 * Nn + c + 1] = v3;
                }
            } else {
                unsigned hi, lo;
                if (r0 < M) {
                    split_pack2(v0, v1, hi, lo);
                    *(unsigned*)&Chp[(size_t)r0 * Nn + c] = hi;
                    *(unsigned*)&Clp[(size_t)r0 * Nn + c] = lo;
                }
                if (r1 < M) {
                    split_pack2(v2, v3, hi, lo);
                    *(unsigned*)&Chp[(size_t)r1 * Nn + c] = hi;
                    *(unsigned*)&Clp[(size_t)r1 * Nn + c] = lo;
                }
            }
        }
    }
}

// ---------------------------------------------------------------------------
// Tensor-core fused 3-phase flash attention with cp.async double-buffered K/V
// and register output accumulation across phases.
// grid = (L1/64, NH), block = 128 (4 warps x 16 query rows).
// ---------------------------------------------------------------------------
#define ATQ 64
#define ASTR 132
#define AQ_ELE (64 * 128)
#define AKV_ELE (32 * 128)
#define ATTN_SMEM ((2 * AQ_ELE + 8 * AKV_ELE) * 2)   // 96 KB

__device__ __forceinline__ int soff(int r, int c8)
{
    return r * 128 + (((c8) ^ (r & 7)) << 3);
}

__global__ __launch_bounds__(128) void attn_mma(
    const __nv_bfloat16* __restrict__ Qh,  const __nv_bfloat16* __restrict__ Ql,
    const __nv_bfloat16* __restrict__ Kth, const __nv_bfloat16* __restrict__ Ktl,
    const __nv_bfloat16* __restrict__ Vth, const __nv_bfloat16* __restrict__ Vtl,
    const __nv_bfloat16* __restrict__ Kih, const __nv_bfloat16* __restrict__ Kil,
    const __nv_bfloat16* __restrict__ Vih, const __nv_bfloat16* __restrict__ Vil,
    const __nv_bfloat16* __restrict__ PKh, const __nv_bfloat16* __restrict__ PKl,
    const __nv_bfloat16* __restrict__ PVh, const __nv_bfloat16* __restrict__ PVl,
    const int* __restrict__ ctx_lens, const int* __restrict__ audio_lens,
    __nv_bfloat16* __restrict__ Ch, __nv_bfloat16* __restrict__ Cl)
{
    extern __shared__ __nv_bfloat16 sm[];
    __nv_bfloat16* sQh = sm;
    __nv_bfloat16* sQl = sQh + AQ_ELE;
    __nv_bfloat16* sKV = sQl + AQ_ELE;           // [2 stages][Kh,Kl,Vh,Vl][4096]

    const int head  = blockIdx.y;
    const int qbase = blockIdx.x * ATQ;
    const int tid   = threadIdx.x;
    const int warp  = tid >> 5;
    const int lane  = tid & 31;
    const int g     = lane >> 2;
    const int tq    = lane & 3;
    const float scale = 0.08838834764831845f;    // 1/sqrt(128)

    // ---- load Q tile (64 x 128, hi+lo) into swizzled smem ----
#pragma unroll
    for (int i = 0; i < 8; i++) {
        int idx = tid + i * 128;
        int r = idx >> 4, c8 = idx & 15;
        size_t go = (size_t)(qbase + r) * Hd + head * Dh + c8 * 8;
        int so = soff(r, c8);
        *(uint4*)&sQh[so] = *(const uint4*)&Qh[go];
        *(uint4*)&sQl[so] = *(const uint4*)&Ql[go];
    }
    __syncthreads();

    float G[16][4];
#pragma unroll
    for (int n = 0; n < 16; n++)
#pragma unroll
        for (int e = 0; e < 4; e++) G[n][e] = 0.f;

    const int frame   = qbase >> 9;
    const int txt_len = ctx_lens[0];
    const int rfrg = lane & 15;
    const int chi  = lane >> 4;

    for (int phase = 0; phase < 3; phase++) {
        const __nv_bfloat16 *KH, *KL, *VH, *VL;
        int klen;
        if (phase == 0)      { KH = Kih; KL = Kil; VH = Vih; VL = Vil; klen = IMG; }
        else if (phase == 1) { KH = Kth; KL = Ktl; VH = Vth; VL = Vtl; klen = txt_len; }
        else {
            size_t fo = (size_t)frame * L3 * Hd;
            KH = PKh + fo; KL = PKl + fo; VH = PVh + fo; VL = PVl + fo;
            klen = audio_lens[frame];
        }
        const int nch = (klen + 31) >> 5;

        // preload chunk 0 -> stage 0
        {
            const int cl = min(32, klen);
#pragma unroll
            for (int a = 0; a < 4; a++) {
                const __nv_bfloat16* src = (a == 0) ? KH : (a == 1) ? KL
                                         : (a == 2) ? VH : VL;
#pragma unroll
                for (int i = 0; i < 4; i++) {
                    int idx = tid + i * 128;
                    int r = idx >> 4, c8 = idx & 15;
                    int grow = (r < cl) ? r : 0;
                    cp_async16(&sKV[a * AKV_ELE + soff(r, c8)],
                               src + (size_t)grow * Hd + head * Dh + c8 * 8,
                               r < cl ? 16 : 0);
                }
            }
            asm volatile("cp.async.commit_group;\n" ::: "memory");
        }

        float m0 = -1e30f, m1 = -1e30f, l0 = 0.f, l1 = 0.f;
        float o[16][4];
#pragma unroll
        for (int n = 0; n < 16; n++)
#pragma unroll
            for (int e = 0; e < 4; e++) o[n][e] = 0.f;

        for (int c = 0; c < nch; c++) {
            const int b = c & 1;
            if (c + 1 < nch) {
                const int kb2 = (c + 1) * 32;
                const int cl2 = min(32, klen - kb2);
#pragma unroll
                for (int a = 0; a < 4; a++) {
                    const __nv_bfloat16* src = (a == 0) ? KH : (a == 1) ? KL
                                             : (a == 2) ? VH : VL;
#pragma unroll
                    for (int i = 0; i < 4; i++) {
                        int idx = tid + i * 128;
                        int r = idx >> 4, c8 = idx & 15;
                        int grow = (r < cl2) ? kb2 + r : 0;
                        cp_async16(&sKV[((b ^ 1) * 4 + a) * AKV_ELE + soff(r, c8)],
                                   src + (size_t)grow * Hd + head * Dh + c8 * 8,
                                   r < cl2 ? 16 : 0);
                    }
                }
                asm volatile("cp.async.commit_group;\n" ::: "memory");
                asm volatile("cp.async.wait_group 1;\n" ::: "memory");
            } else {
                asm volatile("cp.async.wait_group 0;\n" ::: "memory");
            }
            __syncthreads();

            const __nv_bfloat16* pKh = sKV + (b * 4 + 0) * AKV_ELE;
            const __nv_bfloat16* pKl = sKV + (b * 4 + 1) * AKV_ELE;
            const __nv_bfloat16* pVh = sKV + (b * 4 + 2) * AKV_ELE;
            const __nv_bfloat16* pVl = sKV + (b * 4 + 3) * AKV_ELE;
            const int kb = c * 32;

            // ---- S = Q K^T (bf16x3), 16x32 per warp ----
            float sacc[4][4];
#pragma unroll
            for (int n = 0; n < 4; n++)
#pragma unroll
                for (int e = 0; e < 4; e++) sacc[n][e] = 0.f;

#pragma unroll
            for (int ks = 0; ks < 8; ks++) {
                const int c8 = ks * 2 + chi;
                unsigned aqh[4], aql[4];
                ldsm_x4(aqh, &sQh[soff(warp * 16 + rfrg, c8)]);
                ldsm_x4(aql, &sQl[soff(warp * 16 + rfrg, c8)]);

                unsigned kbh[4][2], kbl[4][2];
#pragma unroll
                for (int p = 0; p < 2; p++) {
                    unsigned t[4];
                    ldsm_x4(t, &pKh[soff(p * 16 + rfrg, c8)]);
                    kbh[p*2][0] = t[0]; kbh[p*2+1][0] = t[1];
                    kbh[p*2][1] = t[2]; kbh[p*2+1][1] = t[3];
                    ldsm_x4(t, &pKl[soff(p * 16 + rfrg, c8)]);
                    kbl[p*2][0] = t[0]; kbl[p*2+1][0] = t[1];
                    kbl[p*2][1] = t[2]; kbl[p*2+1][1] = t[3];
                }
#pragma unroll
                for (int n = 0; n < 4; n++) {
                    mma_bf16(sacc[n], aqh, kbh[n]);
                    mma_bf16(sacc[n], aqh, kbl[n]);
                    mma_bf16(sacc[n], aql, kbh[n]);
                }
            }

            // ---- online softmax in fragment layout ----
            float rmax0 = -1e30f, rmax1 = -1e30f;
#pragma unroll
            for (int n = 0; n < 4; n++) {
                int colb = kb + n * 8 + tq * 2;
                bool v0 = colb < klen, v1 = (colb + 1) < klen;
                float x0 = v0 ? sacc[n][0] * scale : -1e30f;
                float x1 = v1 ? sacc[n][1] * scale : -1e30f;
                float x2 = v0 ? sacc[n][2] * scale : -1e30f;
                float x3 = v1 ? sacc[n][3] * scale : -1e30f;
                sacc[n][0] = x0; sacc[n][1] = x1; sacc[n][2] = x2; sacc[n][3] = x3;
                rmax0 = fmaxf(rmax0, fmaxf(x0, x1));
                rmax1 = fmaxf(rmax1, fmaxf(x2, x3));
            }
            rmax0 = fmaxf(rmax0, __shfl_xor_sync(0xffffffffu, rmax0, 1));
            rmax0 = fmaxf(rmax0, __shfl_xor_sync(0xffffffffu, rmax0, 2));
            rmax1 = fmaxf(rmax1, __shfl_xor_sync(0xffffffffu, rmax1, 1));
            rmax1 = fmaxf(rmax1, __shfl_xor_sync(0xffffffffu, rmax1, 2));

            float mn0 = fmaxf(m0, rmax0), mn1 = fmaxf(m1, rmax1);
            float c0 = __expf(m0 - mn0),  c1 = __expf(m1 - mn1);
            float s0 = 0.f, s1 = 0.f;
#pragma unroll
            for (int n = 0; n < 4; n++) {
                float p0 = __expf(sacc[n][0] - mn0);
                float p1 = __expf(sacc[n][1] - mn0);
                float p2 = __expf(sacc[n][2] - mn1);
                float p3 = __expf(sacc[n][3] - mn1);
                sacc[n][0] = p0; sacc[n][1] = p1; sacc[n][2] = p2; sacc[n][3] = p3;
                s0 += p0 + p1; s1 += p2 + p3;
            }
            s0 += __shfl_xor_sync(0xffffffffu, s0, 1);
            s0 += __shfl_xor_sync(0xffffffffu, s0, 2);
            s1 += __shfl_xor_sync(0xffffffffu, s1, 1);
            s1 += __shfl_xor_sync(0xffffffffu, s1, 2);
            l0 = l0 * c0 + s0; l1 = l1 * c1 + s1;
            m0 = mn0; m1 = mn1;

#pragma unroll
            for (int n = 0; n < 16; n++) {
                o[n][0] *= c0; o[n][1] *= c0;
                o[n][2] *= c1; o[n][3] *= c1;
            }

            // ---- P fragments (hi/lo split) ----
            unsigned aPh[2][4], aPl[2][4];
#pragma unroll
            for (int ks = 0; ks < 2; ks++) {
                split_pack2(sacc[2*ks][0],   sacc[2*ks][1],   aPh[ks][0], aPl[ks][0]);
                split_pack2(sacc[2*ks][2],   sacc[2*ks][3],   aPh[ks][1], aPl[ks][1]);
                split_pack2(sacc[2*ks+1][0], sacc[2*ks+1][1], aPh[ks][2], aPl[ks][2]);
                split_pack2(sacc[2*ks+1][2], sacc[2*ks+1][3], aPh[ks][3], aPl[ks][3]);
            }

            // ---- O += P V (bf16x3), V via ldmatrix.trans ----
#pragma unroll
            for (int ks = 0; ks < 2; ks++) {
#pragma unroll
                for (int ntp = 0; ntp < 8; ntp++) {
                    int vr = ks * 16 + ((lane >> 3) & 1) * 8 + (lane & 7);
                    int vc = ntp * 2 + (lane >> 4);
                    unsigned th[4], tl[4];
                    ldsm_x4_t(th, &pVh[soff(vr, vc)]);
                    ldsm_x4_t(tl, &pVl[soff(vr, vc)]);
                    unsigned bh0[2] = {th[0], th[1]};
                    unsigned bh1[2] = {th[2], th[3]};
                    unsigned bl0[2] = {tl[0], tl[1]};
                    unsigned bl1[2] = {tl[2], tl[3]};
                    mma_bf16(o[2*ntp],   aPh[ks], bh0);
                    mma_bf16(o[2*ntp],   aPh[ks], bl0);
                    mma_bf16(o[2*ntp],   aPl[ks], bh0);
                    mma_bf16(o[2*ntp+1], aPh[ks], bh1);
                    mma_bf16(o[2*ntp+1], aPh[ks], bl1);
                    mma_bf16(o[2*ntp+1], aPl[ks], bh1);
                }
            }
            __syncthreads();
        } // chunk

        float rl0 = 1.f / l0, rl1 = 1.f / l1;
#pragma unroll
        for (int n = 0; n < 16; n++) {
            G[n][0] += o[n][0] * rl0; G[n][1] += o[n][1] * rl0;
            G[n][2] += o[n][2] * rl1; G[n][3] += o[n][3] * rl1;
        }
    } // phase

    // ---- stage G through smem (reuse K/V region) for coalesced split write ----
    float* sO = (float*)sKV;
    {
        int row0 = warp * 16 + g;
#pragma unroll
        for (int n = 0; n < 16; n++) {
            int col = n * 8 + tq * 2;
            sO[row0 * ASTR + col]           = G[n][0];
            sO[row0 * ASTR + col + 1]       = G[n][1];
            sO[(row0 + 8) * ASTR + col]     = G[n][2];
            sO[(row0 + 8) * ASTR + col + 1] = G[n][3];
        }
    }
    __syncthreads();
#pragma unroll
    for (int i = 0; i < 16; i++) {
        int idx = tid + i * 128;
        int r = idx >> 5, cb = (idx & 31) * 4;
        float f0 = sO[r * ASTR + cb + 0];
        float f1 = sO[r * ASTR + cb + 1];
        float f2 = sO[r * ASTR + cb + 2];
        float f3 = sO[r * ASTR + cb + 3];
        unsigned h0, l0u, h1, l1u;
        split_pack2(f0, f1, h0, l0u);
        split_pack2(f2, f3, h1, l1u);
        size_t go = (size_t)(qbase + r) * Hd + head * Dh + cb;
        *(uint2*)&Ch[go] = make_uint2(h0, h1);
        *(uint2*)&Cl[go] = make_uint2(l0u, l1u);
    }
}

// ---------------------------------------------------------------------------
// Launch
// ---------------------------------------------------------------------------
static void run_split(const float* src, __nv_bfloat16* hi, __nv_bfloat16* lo, size_t n)
{
    int n4 = (int)(n / 4);
    split_kernel<<<(n4 + 255) / 256, 256>>>(
        (const float4*)src, (uint2*)hi, (uint2*)lo, n4);
}

extern "C" void kernel_launch(void* const* d_in, const int* in_sizes, int n_in,
                              void* d_out, int out_size)
{
    const float* x          = (const float*)d_in[0];
    const float* context    = (const float*)d_in[1];
    const float* audio_proj = (const float*)d_in[2];
    const float* Wq  = (const float*)d_in[3];
    const float* bq  = (const float*)d_in[4];
    const float* Wk  = (const float*)d_in[5];
    const float* bk  = (const float*)d_in[6];
    const float* Wv  = (const float*)d_in[7];
    const float* bv  = (const float*)d_in[8];
    const float* Wki = (const float*)d_in[9];
    const float* bki = (const float*)d_in[10];
    const float* Wvi = (const float*)d_in[11];
    const float* bvi = (const float*)d_in[12];
    const float* Wo  = (const float*)d_in[13];
    const float* bo  = (const float*)d_in[14];
    const float* nq  = (const float*)d_in[15];
    const float* nk  = (const float*)d_in[16];
    const float* nki = (const float*)d_in[17];
    const float* Wkp = (const float*)d_in[18];
    const float* Wvp = (const float*)d_in[19];
    const int* ctx_lens   = (const int*)d_in[20];
    const int* audio_lens = (const int*)d_in[21];
    float* out = (float*)d_out;

    float *gQ, *gK, *gKi;
    cudaGetSymbolAddress((void**)&gQ,  g_Q);
    cudaGetSymbolAddress((void**)&gK,  g_K);
    cudaGetSymbolAddress((void**)&gKi, g_Kimg);

    __nv_bfloat16 *xh, *xl, *cth, *ctl, *aph, *apl, *Wh, *Wl, *Wph, *Wpl, *Chh, *Cll;
    cudaGetSymbolAddress((void**)&xh,  g_xh);
    cudaGetSymbolAddress((void**)&xl,  g_xl);
    cudaGetSymbolAddress((void**)&cth, g_cth);
    cudaGetSymbolAddress((void**)&ctl, g_ctl);
    cudaGetSymbolAddress((void**)&aph, g_aph);
    cudaGetSymbolAddress((void**)&apl, g_apl);
    cudaGetSymbolAddress((void**)&Wh,  g_Wh);
    cudaGetSymbolAddress((void**)&Wl,  g_Wl);
    cudaGetSymbolAddress((void**)&Wph, g_Wph);
    cudaGetSymbolAddress((void**)&Wpl, g_Wpl);
    cudaGetSymbolAddress((void**)&Chh, g_Ch);
    cudaGetSymbolAddress((void**)&Cll, g_Cl);

    __nv_bfloat16 *Qh, *Ql, *Kh, *Kl, *Vh, *Vl, *Kih, *Kil, *Vih, *Vil,
                  *PKh, *PKl, *PVh, *PVl;
    cudaGetSymbolAddress((void**)&Qh,  g_Qh);
    cudaGetSymbolAddress((void**)&Ql,  g_Ql);
    cudaGetSymbolAddress((void**)&Kh,  g_Kh);
    cudaGetSymbolAddress((void**)&Kl,  g_Kl);
    cudaGetSymbolAddress((void**)&Vh,  g_Vh);
    cudaGetSymbolAddress((void**)&Vl,  g_Vl);
    cudaGetSymbolAddress((void**)&Kih, g_Kih);
    cudaGetSymbolAddress((void**)&Kil, g_Kil);
    cudaGetSymbolAddress((void**)&Vih, g_Vih);
    cudaGetSymbolAddress((void**)&Vil, g_Vil);
    cudaGetSymbolAddress((void**)&PKh, g_PKh);
    cudaGetSymbolAddress((void**)&PKl, g_PKl);
    cudaGetSymbolAddress((void**)&PVh, g_PVh);
    cudaGetSymbolAddress((void**)&PVl, g_PVl);

    cudaFuncSetAttribute(attn_mma, cudaFuncAttributeMaxDynamicSharedMemorySize,
                         ATTN_SMEM);

    const size_t WSZ  = (size_t)Hd * Hd;
    const size_t WPSZ = (size_t)Hd * CAd;

    // ---- split GEMM inputs ----
    run_split(x,          xh,  xl,  (size_t)L1 * Hd);
    run_split(context,    cth, ctl, (size_t)L2 * Hd);
    run_split(audio_proj, aph, apl, (size_t)NF * L3 * CAd);
    run_split(Wq,  Wh + 0 * WSZ, Wl + 0 * WSZ, WSZ);
    run_split(Wk,  Wh + 1 * WSZ, Wl + 1 * WSZ, WSZ);
    run_split(Wv,  Wh + 2 * WSZ, Wl + 2 * WSZ, WSZ);
    run_split(Wki, Wh + 3 * WSZ, Wl + 3 * WSZ, WSZ);
    run_split(Wvi, Wh + 4 * WSZ, Wl + 4 * WSZ, WSZ);
    run_split(Wo,  Wh + 5 * WSZ, Wl + 5 * WSZ, WSZ);
    run_split(Wkp, Wph + 0 * WPSZ, Wpl + 0 * WPSZ, WPSZ);
    run_split(Wvp, Wph + 1 * WPSZ, Wpl + 1 * WPSZ, WPSZ);

    const __nv_bfloat16* ctxth = cth + (size_t)IMG * Hd;
    const __nv_bfloat16* ctxtl = ctl + (size_t)IMG * Hd;

    // ---- Q projection + norm/split ----
    gemm_pipe<<<dim3(Hd / GBN, L1 / GBM), 256>>>(
        xh, xl, Wh + 0 * WSZ, Wl + 0 * WSZ, bq, gQ, L1, Hd, Hd);
    rmsnorm_split<<<L1, 256>>>(gQ, nq, Qh, Ql);

    // ---- K/V (txt) dual projection ----
    gemm_dual<<<dim3(2 * (Hd / GBN), LTXT / GBM), 256>>>(
        ctxth, ctxtl,
        Wh + 1 * WSZ, Wl + 1 * WSZ, bk, gK, nullptr, nullptr,
        Wh + 2 * WSZ, Wl + 2 * WSZ, bv, nullptr, Vh, Vl,
        LTXT, Hd, Hd);
    rmsnorm_split<<<LTXT, 256>>>(gK, nk, Kh, Kl);

    // ---- K/V (img) dual projection ----
    gemm_dual<<<dim3(2 * (Hd / GBN), (IMG + GBM - 1) / GBM), 256>>>(
        cth, ctl,
        Wh + 3 * WSZ, Wl + 3 * WSZ, bki, gKi, nullptr, nullptr,
        Wh + 4 * WSZ, Wl + 4 * WSZ, bvi, nullptr, Vih, Vil,
        IMG, Hd, Hd);
    rmsnorm_split<<<IMG, 256>>>(gKi, nki, Kih, Kil);

    // ---- audio K/V dual projection (both split outputs, no bias) ----
    const int AM = NF * L3;   // 672
    gemm_dual<<<dim3(2 * (Hd / GBN), (AM + GBM - 1) / GBM), 256>>>(
        aph, apl,
        Wph + 0 * WPSZ, Wpl + 0 * WPSZ, nullptr, nullptr, PKh, PKl,
        Wph + 1 * WPSZ, Wpl + 1 * WPSZ, nullptr, nullptr, PVh, PVl,
        AM, Hd, CAd);

    // ---- tensor-core fused attention -> bf16 hi/lo combined ----
    attn_mma<<<dim3(L1 / ATQ, NH), 128, ATTN_SMEM>>>(
        Qh, Ql, Kh, Kl, Vh, Vl, Kih, Kil, Vih, Vil, PKh, PKl, PVh, PVl,
        ctx_lens, audio_lens, Chh, Cll);

    // ---- output projection ----
    gemm_pipe<<<dim3(Hd / GBN, L1 / GBM), 256>>>(
        Chh, Cll, Wh + 5 * WSZ, Wl + 5 * WSZ, bo, out, L1, Hd, Hd);
}